// round 4
// baseline (speedup 1.0000x reference)
#include <cuda_runtime.h>

typedef unsigned long long u64;

#define Bn   64
#define Cn   256
#define HWn  32
#define PXn  1024
#define C1n  256
#define OCn  1024

// ---------------- scratch (device globals; no allocation allowed) ----------
__device__ __align__(16) float g_h[Bn * C1n * PXn];          // 67 MB  [b][c1][px]
__device__ __align__(16) float g_k[(size_t)Bn * PXn * OCn];  // 268 MB [b][ij][uv]
__device__ float g_p1s[8 * C1n],  g_p1q[8 * C1n];
__device__ float g_a1[C1n], g_b1[C1n];
__device__ float g_p2s[16 * OCn], g_p2q[16 * OCn];
__device__ __align__(16) float g_a2[OCn];
__device__ __align__(16) float g_b2[OCn];

// ---------------- packed fp32x2 helpers ------------------------------------
__device__ __forceinline__ u64 pack2(float lo, float hi) {
    u64 r; asm("mov.b64 %0, {%1, %2};" : "=l"(r) : "f"(lo), "f"(hi)); return r;
}
__device__ __forceinline__ u64 fma2(u64 a, u64 b, u64 c) {
    u64 d; asm("fma.rn.f32x2 %0, %1, %2, %3;" : "=l"(d) : "l"(a), "l"(b), "l"(c)); return d;
}
__device__ __forceinline__ float2 unpack2(u64 v) {
    float2 f; asm("mov.b64 {%0, %1}, %2;" : "=f"(f.x), "=f"(f.y) : "l"(v)); return f;
}

// ============================================================================
// K1: conv1 7x7 dilation-2 pad-6, via 4 parity subgrids (16x16, 7x7 pad-3).
// Block: (ocb of 64 out-ch) x (parity) x (batch). 256 threads.
// Thread: 8 pixels x 8 out-channels, f32x2 paired over channels.
// ============================================================================
__global__ void __launch_bounds__(256, 2)
k_conv1(const float* __restrict__ x, const float* __restrict__ w1,
        const float* __restrict__ cb1) {
    __shared__ __align__(16) float xs[22 * 23];   // subgrid + halo, padded rows
    __shared__ __align__(16) float ws[49 * 64];   // [tap][oc], oc contiguous

    const int tid = threadIdx.x;
    const int ocb = blockIdx.x * 64;
    const int pi  = blockIdx.y >> 1, pj = blockIdx.y & 1;
    const int b   = blockIdx.z;

    const int pxg = tid & 31;          // 32 pixel groups
    const int ocg = tid >> 5;          // 8 channel groups (8 oc each)
    const int si  = pxg >> 1;          // subgrid row 0..15
    const int sj0 = (pxg & 1) * 8;     // subgrid col base 0 or 8

    u64 acc[8][4];
#pragma unroll
    for (int p = 0; p < 8; p++)
#pragma unroll
        for (int q = 0; q < 4; q++) acc[p][q] = 0ull;

    const float* xb = x + (size_t)b * Cn * PXn;

#pragma unroll 1
    for (int cin = 0; cin < Cn; ++cin) {
        __syncthreads();
        // load input subgrid with halo (zero padded)
        const float* xc = xb + cin * PXn;
        for (int idx = tid; idx < 484; idx += 256) {
            int r = idx / 22, cc = idx - r * 22;
            int sgi = r - 3, sgj = cc - 3;
            float v = 0.f;
            if ((unsigned)sgi < 16u && (unsigned)sgj < 16u)
                v = xc[(2 * sgi + pi) * HWn + (2 * sgj + pj)];
            xs[r * 23 + cc] = v;
        }
        // load 64 oc x 49 taps of weights for this cin, layout [tap][oc]
        const float* wc = w1 + cin * 49;
        for (int idx = tid; idx < 3136; idx += 256) {
            int oc = idx / 49, tap = idx - oc * 49;
            ws[tap * 64 + oc] = wc[(size_t)(ocb + oc) * (Cn * 49) + tap];
        }
        __syncthreads();

#pragma unroll 1
        for (int kh = 0; kh < 7; ++kh) {
            const float* xrow = &xs[(si + kh) * 23 + sj0];
            const float* wrow = &ws[kh * 7 * 64 + ocg * 8];
#pragma unroll
            for (int kw = 0; kw < 7; ++kw) {
                u64 wp[4];
#pragma unroll
                for (int q = 0; q < 4; q++)
                    wp[q] = *reinterpret_cast<const u64*>(wrow + kw * 64 + 2 * q);
#pragma unroll
                for (int p = 0; p < 8; p++) {
                    float xv = xrow[kw + p];
                    u64 xx = pack2(xv, xv);
#pragma unroll
                    for (int q = 0; q < 4; q++) acc[p][q] = fma2(xx, wp[q], acc[p][q]);
                }
            }
        }
    }

    // epilogue: + conv1 bias, store into h[b][oc][fi*32+fj]
    const int fi = 2 * si + pi;
#pragma unroll
    for (int q = 0; q < 4; q++) {
        int oc0 = ocb + ocg * 8 + 2 * q;
        float bz0 = cb1[oc0], bz1 = cb1[oc0 + 1];
        float* h0 = g_h + ((size_t)b * C1n + oc0) * PXn;
        float* h1 = h0 + PXn;
#pragma unroll
        for (int p = 0; p < 8; p++) {
            float2 v = unpack2(acc[p][q]);
            int fj = 2 * (sj0 + p) + pj;
            h0[fi * HWn + fj] = v.x + bz0;
            h1[fi * HWn + fj] = v.y + bz1;
        }
    }
}

// ============================================================================
// K2/K3: BN1 batch stats (deterministic two-stage reduction) + finalize
// ============================================================================
__global__ void __launch_bounds__(256) k_stats1() {
    const int c = blockIdx.x;
    const int b0 = blockIdx.y * 8;
    float s = 0.f, q = 0.f;
    for (int b = b0; b < b0 + 8; ++b) {
        const float* hp = g_h + ((size_t)b * C1n + c) * PXn;
        for (int px = threadIdx.x; px < PXn; px += 256) {
            float v = hp[px]; s += v; q += v * v;
        }
    }
    __shared__ float ss[256], qs[256];
    ss[threadIdx.x] = s; qs[threadIdx.x] = q;
    __syncthreads();
    for (int o = 128; o > 0; o >>= 1) {
        if (threadIdx.x < o) {
            ss[threadIdx.x] += ss[threadIdx.x + o];
            qs[threadIdx.x] += qs[threadIdx.x + o];
        }
        __syncthreads();
    }
    if (threadIdx.x == 0) {
        g_p1s[blockIdx.y * C1n + c] = ss[0];
        g_p1q[blockIdx.y * C1n + c] = qs[0];
    }
}

__global__ void k_fin1(const float* __restrict__ g, const float* __restrict__ bb) {
    const int c = threadIdx.x;
    float s = 0.f, q = 0.f;
#pragma unroll
    for (int i = 0; i < 8; i++) { s += g_p1s[i * C1n + c]; q += g_p1q[i * C1n + c]; }
    const float inv = 1.0f / 65536.0f;
    float m = s * inv;
    float var = q * inv - m * m;
    float a = g[c] * rsqrtf(var + 1e-5f);
    g_a1[c] = a;
    g_b1[c] = bb[c] - m * a;
}

// ============================================================================
// K4: conv2 1x1 GEMM per batch: k[oc][px] = W2[oc][c] * (a1*h+b1)[c][px] + b2
// 128x128 tile, K-chunk 16, f32x2 paired over oc. Output stored transposed
// as g_k[b][px][oc] so softmax & final GEMM get contiguous rows.
// ============================================================================
__global__ void __launch_bounds__(256, 2)
k_conv2(const float* __restrict__ w2, const float* __restrict__ cb2) {
    __shared__ __align__(16) float As[16 * 130];  // [kk][oc]  stride 130
    __shared__ __align__(16) float Bs[16 * 128];  // [kk][px]  stride 128
    const int tid = threadIdx.x;
    const int pxb = blockIdx.x * 128, ocb = blockIdx.y * 128, b = blockIdx.z;
    const int tx = tid & 15, ty = tid >> 4;
    const int px0 = tx * 8, oc0 = ty * 8;

    u64 acc[8][4];
#pragma unroll
    for (int p = 0; p < 8; p++)
#pragma unroll
        for (int q = 0; q < 4; q++) acc[p][q] = 0ull;

#pragma unroll 1
    for (int k0 = 0; k0 < C1n; k0 += 16) {
        __syncthreads();
#pragma unroll
        for (int it = 0; it < 8; ++it) {
            int idx = tid + it * 256;
            int kk = idx & 15, oc = idx >> 4;
            As[kk * 130 + oc] = w2[(size_t)(ocb + oc) * C1n + k0 + kk];
        }
#pragma unroll
        for (int it = 0; it < 8; ++it) {
            int idx = tid + it * 256;
            int px = idx & 127, kk = idx >> 7;
            int c = k0 + kk;
            float hv = g_h[((size_t)b * C1n + c) * PXn + pxb + px];
            Bs[kk * 128 + px] = g_a1[c] * hv + g_b1[c];
        }
        __syncthreads();
#pragma unroll
        for (int kk = 0; kk < 16; kk++) {
            float4 bA = *reinterpret_cast<const float4*>(&Bs[kk * 128 + px0]);
            float4 bB = *reinterpret_cast<const float4*>(&Bs[kk * 128 + px0 + 4]);
            u64 wp[4];
#pragma unroll
            for (int q = 0; q < 4; q++)
                wp[q] = *reinterpret_cast<const u64*>(&As[kk * 130 + oc0 + 2 * q]);
            float bv[8] = {bA.x, bA.y, bA.z, bA.w, bB.x, bB.y, bB.z, bB.w};
#pragma unroll
            for (int p = 0; p < 8; p++) {
                u64 xx = pack2(bv[p], bv[p]);
#pragma unroll
                for (int q = 0; q < 4; q++) acc[p][q] = fma2(xx, wp[q], acc[p][q]);
            }
        }
    }

    float* kb = g_k + (size_t)b * PXn * OCn;
#pragma unroll
    for (int q = 0; q < 4; q++) {
        int oc = ocb + oc0 + 2 * q;
        float c0v = cb2[oc], c1v = cb2[oc + 1];
#pragma unroll
        for (int p = 0; p < 8; p++) {
            int px = pxb + px0 + p;
            float2 v = unpack2(acc[p][q]);
            float2 o; o.x = v.x + c0v; o.y = v.y + c1v;
            *reinterpret_cast<float2*>(&kb[(size_t)px * OCn + oc]) = o;
        }
    }
}

// ============================================================================
// K5/K6: BN2 stats (coalesced over oc-minor layout) + finalize
// ============================================================================
__global__ void __launch_bounds__(256) k_stats2() {
    const int lane = threadIdx.x & 31, row = threadIdx.x >> 5;  // 8 rows x 32 oc
    const int oc = blockIdx.x * 32 + lane;
    const int r0 = blockIdx.y * 4096;
    float s = 0.f, q = 0.f;
    for (int r = r0 + row; r < r0 + 4096; r += 8) {
        float v = g_k[(size_t)r * OCn + oc];
        s += v; q += v * v;
    }
    __shared__ float ss[8][33], qs[8][33];
    ss[row][lane] = s; qs[row][lane] = q;
    __syncthreads();
    if (row == 0) {
#pragma unroll
        for (int i = 1; i < 8; i++) { s += ss[i][lane]; q += qs[i][lane]; }
        g_p2s[blockIdx.y * OCn + oc] = s;
        g_p2q[blockIdx.y * OCn + oc] = q;
    }
}

__global__ void k_fin2(const float* __restrict__ g, const float* __restrict__ bb) {
    const int oc = threadIdx.x;
    float s = 0.f, q = 0.f;
#pragma unroll
    for (int i = 0; i < 16; i++) { s += g_p2s[i * OCn + oc]; q += g_p2q[i * OCn + oc]; }
    const float inv = 1.0f / 65536.0f;
    float m = s * inv;
    float var = q * inv - m * m;
    float a = g[oc] * rsqrtf(var + 1e-5f);
    g_a2[oc] = a;
    g_b2[oc] = bb[oc] - m * a;
}

// ============================================================================
// K7: fused BN2-affine + softmax over the 1024 uv channels (contiguous rows)
// ============================================================================
__global__ void __launch_bounds__(128) k_softmax() {
    __shared__ float red[8];
    float* row = g_k + (size_t)blockIdx.x * OCn;
    const int t = threadIdx.x;
    const int lane = t & 31, wid = t >> 5;

    float4 v0 = *reinterpret_cast<float4*>(row + t * 4);
    float4 v1 = *reinterpret_cast<float4*>(row + 512 + t * 4);
    float4 a0 = *reinterpret_cast<const float4*>(g_a2 + t * 4);
    float4 a1 = *reinterpret_cast<const float4*>(g_a2 + 512 + t * 4);
    float4 b0 = *reinterpret_cast<const float4*>(g_b2 + t * 4);
    float4 b1 = *reinterpret_cast<const float4*>(g_b2 + 512 + t * 4);

    float z[8];
    z[0] = a0.x * v0.x + b0.x; z[1] = a0.y * v0.y + b0.y;
    z[2] = a0.z * v0.z + b0.z; z[3] = a0.w * v0.w + b0.w;
    z[4] = a1.x * v1.x + b1.x; z[5] = a1.y * v1.y + b1.y;
    z[6] = a1.z * v1.z + b1.z; z[7] = a1.w * v1.w + b1.w;

    float m = z[0];
#pragma unroll
    for (int i = 1; i < 8; i++) m = fmaxf(m, z[i]);
#pragma unroll
    for (int o = 16; o > 0; o >>= 1) m = fmaxf(m, __shfl_xor_sync(0xffffffffu, m, o));
    if (lane == 0) red[wid] = m;
    __syncthreads();
    m = fmaxf(fmaxf(red[0], red[1]), fmaxf(red[2], red[3]));

    float s = 0.f;
#pragma unroll
    for (int i = 0; i < 8; i++) { z[i] = __expf(z[i] - m); s += z[i]; }
#pragma unroll
    for (int o = 16; o > 0; o >>= 1) s += __shfl_xor_sync(0xffffffffu, s, o);
    if (lane == 0) red[4 + wid] = s;
    __syncthreads();
    s = (red[4] + red[5]) + (red[6] + red[7]);
    float inv = 1.0f / s;

    v0 = make_float4(z[0] * inv, z[1] * inv, z[2] * inv, z[3] * inv);
    v1 = make_float4(z[4] * inv, z[5] * inv, z[6] * inv, z[7] * inv);
    *reinterpret_cast<float4*>(row + t * 4) = v0;
    *reinterpret_cast<float4*>(row + 512 + t * 4) = v1;
}

// ============================================================================
// K8: final einsum GEMM per batch:
//   out[b][ij][c] = sum_uv kmap[b][ij][uv] * x[b][c][uv]
// A = g_k rows (contiguous), B = x transposed via smem. Output buffer IS
// y[b,i,j,c] row-major (the reference does a raw reshape).
// ============================================================================
__global__ void __launch_bounds__(256, 2)
k_final(const float* __restrict__ x, float* __restrict__ out) {
    __shared__ __align__(16) float As[16 * 130];  // [kk][ij]
    __shared__ __align__(16) float Bs[16 * 130];  // [kk][c]
    const int tid = threadIdx.x;
    const int cb = blockIdx.x * 128, ijb = blockIdx.y * 128, b = blockIdx.z;
    const int tx = tid & 15, ty = tid >> 4;
    const int ij0 = tx * 8, c0 = ty * 8;

    u64 acc[8][4];
#pragma unroll
    for (int p = 0; p < 8; p++)
#pragma unroll
        for (int q = 0; q < 4; q++) acc[p][q] = 0ull;

    const float* kb = g_k + (size_t)b * PXn * OCn;
    const float* xb = x + (size_t)b * Cn * PXn;

#pragma unroll 1
    for (int u0 = 0; u0 < OCn; u0 += 16) {
        __syncthreads();
#pragma unroll
        for (int it = 0; it < 8; ++it) {
            int idx = tid + it * 256;
            int kk = idx & 15, ij = idx >> 4;
            As[kk * 130 + ij] = kb[(size_t)(ijb + ij) * OCn + u0 + kk];
        }
#pragma unroll
        for (int it = 0; it < 8; ++it) {
            int idx = tid + it * 256;
            int kk = idx & 15, c = idx >> 4;
            Bs[kk * 130 + c] = xb[(size_t)(cb + c) * PXn + u0 + kk];
        }
        __syncthreads();
#pragma unroll
        for (int kk = 0; kk < 16; kk++) {
            u64 wp[4];
#pragma unroll
            for (int q = 0; q < 4; q++)
                wp[q] = *reinterpret_cast<const u64*>(&Bs[kk * 130 + c0 + 2 * q]);
#pragma unroll
            for (int p = 0; p < 8; p++) {
                float av = As[kk * 130 + ij0 + p];
                u64 xx = pack2(av, av);
#pragma unroll
                for (int q = 0; q < 4; q++) acc[p][q] = fma2(xx, wp[q], acc[p][q]);
            }
        }
    }

    float* ob = out + (size_t)b * PXn * Cn;
#pragma unroll
    for (int p = 0; p < 8; p++) {
        int ij = ijb + ij0 + p;
#pragma unroll
        for (int q = 0; q < 4; q++) {
            float2 v = unpack2(acc[p][q]);
            *reinterpret_cast<float2*>(&ob[(size_t)ij * Cn + cb + c0 + 2 * q]) = v;
        }
    }
}

// ============================================================================
extern "C" void kernel_launch(void* const* d_in, const int* in_sizes, int n_in,
                              void* d_out, int out_size) {
    (void)in_sizes; (void)n_in; (void)out_size;
    const float* x   = (const float*)d_in[0];
    const float* w1  = (const float*)d_in[1];
    const float* cb1 = (const float*)d_in[2];
    const float* g1  = (const float*)d_in[3];
    const float* bb1 = (const float*)d_in[4];
    const float* w2  = (const float*)d_in[5];
    const float* cb2 = (const float*)d_in[6];
    const float* g2  = (const float*)d_in[7];
    const float* bb2 = (const float*)d_in[8];
    float* out = (float*)d_out;

    k_conv1  <<<dim3(4, 4, Bn), 256>>>(x, w1, cb1);
    k_stats1 <<<dim3(C1n, 8), 256>>>();
    k_fin1   <<<1, C1n>>>(g1, bb1);
    k_conv2  <<<dim3(8, 8, Bn), 256>>>(w2, cb2);
    k_stats2 <<<dim3(32, 16), 256>>>();
    k_fin2   <<<1, OCn>>>(g2, bb2);
    k_softmax<<<Bn * PXn, 128>>>();
    k_final  <<<dim3(2, 8, Bn), 256>>>(x, out);
}

// round 7
// speedup vs baseline: 1.0001x; 1.0001x over previous
#include <cuda_runtime.h>

typedef unsigned long long u64;

#define Bn   64
#define Cn   256
#define HWn  32
#define PXn  1024
#define C1n  256
#define OCn  1024

// ---------------- scratch (device globals; no allocation allowed) ----------
__device__ __align__(16) float g_h[Bn * C1n * PXn];          // 67 MB  [b][c1][px]
__device__ __align__(16) float g_k[(size_t)Bn * PXn * OCn];  // 268 MB [b][ij][uv]
__device__ float g_p1s[8 * C1n],  g_p1q[8 * C1n];
__device__ float g_a1[C1n], g_b1[C1n];
__device__ float g_p2s[16 * OCn], g_p2q[16 * OCn];
__device__ __align__(16) float g_a2[OCn];
__device__ __align__(16) float g_b2[OCn];

// ---------------- packed fp32x2 helpers ------------------------------------
__device__ __forceinline__ u64 pack2(float lo, float hi) {
    u64 r; asm("mov.b64 %0, {%1, %2};" : "=l"(r) : "f"(lo), "f"(hi)); return r;
}
__device__ __forceinline__ u64 fma2(u64 a, u64 b, u64 c) {
    u64 d; asm("fma.rn.f32x2 %0, %1, %2, %3;" : "=l"(d) : "l"(a), "l"(b), "l"(c)); return d;
}
__device__ __forceinline__ float2 unpack2(u64 v) {
    float2 f; asm("mov.b64 {%0, %1}, %2;" : "=f"(f.x), "=f"(f.y) : "l"(v)); return f;
}

// ============================================================================
// K1: conv1 7x7 dilation-2 pad-6, via 4 parity subgrids (16x16, 7x7 pad-3).
// Block: (ocb of 64 out-ch) x (parity) x (batch). 256 threads.
// Thread: 8 pixels x 8 out-channels, f32x2 paired over channels.
// ============================================================================
__global__ void __launch_bounds__(256, 2)
k_conv1(const float* __restrict__ x, const float* __restrict__ w1,
        const float* __restrict__ cb1) {
    __shared__ __align__(16) float xs[22 * 23];   // subgrid + halo, padded rows
    __shared__ __align__(16) float ws[49 * 64];   // [tap][oc], oc contiguous

    const int tid = threadIdx.x;
    const int ocb = blockIdx.x * 64;
    const int pi  = blockIdx.y >> 1, pj = blockIdx.y & 1;
    const int b   = blockIdx.z;

    const int pxg = tid & 31;          // 32 pixel groups
    const int ocg = tid >> 5;          // 8 channel groups (8 oc each)
    const int si  = pxg >> 1;          // subgrid row 0..15
    const int sj0 = (pxg & 1) * 8;     // subgrid col base 0 or 8

    u64 acc[8][4];
#pragma unroll
    for (int p = 0; p < 8; p++)
#pragma unroll
        for (int q = 0; q < 4; q++) acc[p][q] = 0ull;

    const float* xb = x + (size_t)b * Cn * PXn;

#pragma unroll 1
    for (int cin = 0; cin < Cn; ++cin) {
        __syncthreads();
        // load input subgrid with halo (zero padded)
        const float* xc = xb + cin * PXn;
        for (int idx = tid; idx < 484; idx += 256) {
            int r = idx / 22, cc = idx - r * 22;
            int sgi = r - 3, sgj = cc - 3;
            float v = 0.f;
            if ((unsigned)sgi < 16u && (unsigned)sgj < 16u)
                v = xc[(2 * sgi + pi) * HWn + (2 * sgj + pj)];
            xs[r * 23 + cc] = v;
        }
        // load 64 oc x 49 taps of weights for this cin, layout [tap][oc]
        const float* wc = w1 + cin * 49;
        for (int idx = tid; idx < 3136; idx += 256) {
            int oc = idx / 49, tap = idx - oc * 49;
            ws[tap * 64 + oc] = wc[(size_t)(ocb + oc) * (Cn * 49) + tap];
        }
        __syncthreads();

#pragma unroll 1
        for (int kh = 0; kh < 7; ++kh) {
            const float* xrow = &xs[(si + kh) * 23 + sj0];
            const float* wrow = &ws[kh * 7 * 64 + ocg * 8];
#pragma unroll
            for (int kw = 0; kw < 7; ++kw) {
                u64 wp[4];
#pragma unroll
                for (int q = 0; q < 4; q++)
                    wp[q] = *reinterpret_cast<const u64*>(wrow + kw * 64 + 2 * q);
#pragma unroll
                for (int p = 0; p < 8; p++) {
                    float xv = xrow[kw + p];
                    u64 xx = pack2(xv, xv);
#pragma unroll
                    for (int q = 0; q < 4; q++) acc[p][q] = fma2(xx, wp[q], acc[p][q]);
                }
            }
        }
    }

    // epilogue: + conv1 bias, store into h[b][oc][fi*32+fj]
    const int fi = 2 * si + pi;
#pragma unroll
    for (int q = 0; q < 4; q++) {
        int oc0 = ocb + ocg * 8 + 2 * q;
        float bz0 = cb1[oc0], bz1 = cb1[oc0 + 1];
        float* h0 = g_h + ((size_t)b * C1n + oc0) * PXn;
        float* h1 = h0 + PXn;
#pragma unroll
        for (int p = 0; p < 8; p++) {
            float2 v = unpack2(acc[p][q]);
            int fj = 2 * (sj0 + p) + pj;
            h0[fi * HWn + fj] = v.x + bz0;
            h1[fi * HWn + fj] = v.y + bz1;
        }
    }
}

// ============================================================================
// K2/K3: BN1 batch stats (deterministic two-stage reduction) + finalize
// ============================================================================
__global__ void __launch_bounds__(256) k_stats1() {
    const int c = blockIdx.x;
    const int b0 = blockIdx.y * 8;
    float s = 0.f, q = 0.f;
    for (int b = b0; b < b0 + 8; ++b) {
        const float* hp = g_h + ((size_t)b * C1n + c) * PXn;
        for (int px = threadIdx.x; px < PXn; px += 256) {
            float v = hp[px]; s += v; q += v * v;
        }
    }
    __shared__ float ss[256], qs[256];
    ss[threadIdx.x] = s; qs[threadIdx.x] = q;
    __syncthreads();
    for (int o = 128; o > 0; o >>= 1) {
        if (threadIdx.x < o) {
            ss[threadIdx.x] += ss[threadIdx.x + o];
            qs[threadIdx.x] += qs[threadIdx.x + o];
        }
        __syncthreads();
    }
    if (threadIdx.x == 0) {
        g_p1s[blockIdx.y * C1n + c] = ss[0];
        g_p1q[blockIdx.y * C1n + c] = qs[0];
    }
}

__global__ void k_fin1(const float* __restrict__ g, const float* __restrict__ bb) {
    const int c = threadIdx.x;
    float s = 0.f, q = 0.f;
#pragma unroll
    for (int i = 0; i < 8; i++) { s += g_p1s[i * C1n + c]; q += g_p1q[i * C1n + c]; }
    const float inv = 1.0f / 65536.0f;
    float m = s * inv;
    float var = q * inv - m * m;
    float a = g[c] * rsqrtf(var + 1e-5f);
    g_a1[c] = a;
    g_b1[c] = bb[c] - m * a;
}

// ============================================================================
// K4: conv2 1x1 GEMM per batch: k[oc][px] = W2[oc][c] * (a1*h+b1)[c][px] + b2
// 128x128 tile, K-chunk 16, f32x2 paired over oc. Output stored transposed
// as g_k[b][px][oc] so softmax & final GEMM get contiguous rows.
// ============================================================================
__global__ void __launch_bounds__(256, 2)
k_conv2(const float* __restrict__ w2, const float* __restrict__ cb2) {
    __shared__ __align__(16) float As[16 * 130];  // [kk][oc]  stride 130
    __shared__ __align__(16) float Bs[16 * 128];  // [kk][px]  stride 128
    const int tid = threadIdx.x;
    const int pxb = blockIdx.x * 128, ocb = blockIdx.y * 128, b = blockIdx.z;
    const int tx = tid & 15, ty = tid >> 4;
    const int px0 = tx * 8, oc0 = ty * 8;

    u64 acc[8][4];
#pragma unroll
    for (int p = 0; p < 8; p++)
#pragma unroll
        for (int q = 0; q < 4; q++) acc[p][q] = 0ull;

#pragma unroll 1
    for (int k0 = 0; k0 < C1n; k0 += 16) {
        __syncthreads();
#pragma unroll
        for (int it = 0; it < 8; ++it) {
            int idx = tid + it * 256;
            int kk = idx & 15, oc = idx >> 4;
            As[kk * 130 + oc] = w2[(size_t)(ocb + oc) * C1n + k0 + kk];
        }
#pragma unroll
        for (int it = 0; it < 8; ++it) {
            int idx = tid + it * 256;
            int px = idx & 127, kk = idx >> 7;
            int c = k0 + kk;
            float hv = g_h[((size_t)b * C1n + c) * PXn + pxb + px];
            Bs[kk * 128 + px] = g_a1[c] * hv + g_b1[c];
        }
        __syncthreads();
#pragma unroll
        for (int kk = 0; kk < 16; kk++) {
            float4 bA = *reinterpret_cast<const float4*>(&Bs[kk * 128 + px0]);
            float4 bB = *reinterpret_cast<const float4*>(&Bs[kk * 128 + px0 + 4]);
            u64 wp[4];
#pragma unroll
            for (int q = 0; q < 4; q++)
                wp[q] = *reinterpret_cast<const u64*>(&As[kk * 130 + oc0 + 2 * q]);
            float bv[8] = {bA.x, bA.y, bA.z, bA.w, bB.x, bB.y, bB.z, bB.w};
#pragma unroll
            for (int p = 0; p < 8; p++) {
                u64 xx = pack2(bv[p], bv[p]);
#pragma unroll
                for (int q = 0; q < 4; q++) acc[p][q] = fma2(xx, wp[q], acc[p][q]);
            }
        }
    }

    float* kb = g_k + (size_t)b * PXn * OCn;
#pragma unroll
    for (int q = 0; q < 4; q++) {
        int oc = ocb + oc0 + 2 * q;
        float c0v = cb2[oc], c1v = cb2[oc + 1];
#pragma unroll
        for (int p = 0; p < 8; p++) {
            int px = pxb + px0 + p;
            float2 v = unpack2(acc[p][q]);
            float2 o; o.x = v.x + c0v; o.y = v.y + c1v;
            *reinterpret_cast<float2*>(&kb[(size_t)px * OCn + oc]) = o;
        }
    }
}

// ============================================================================
// K5/K6: BN2 stats (coalesced over oc-minor layout) + finalize
// ============================================================================
__global__ void __launch_bounds__(256) k_stats2() {
    const int lane = threadIdx.x & 31, row = threadIdx.x >> 5;  // 8 rows x 32 oc
    const int oc = blockIdx.x * 32 + lane;
    const int r0 = blockIdx.y * 4096;
    float s = 0.f, q = 0.f;
    for (int r = r0 + row; r < r0 + 4096; r += 8) {
        float v = g_k[(size_t)r * OCn + oc];
        s += v; q += v * v;
    }
    __shared__ float ss[8][33], qs[8][33];
    ss[row][lane] = s; qs[row][lane] = q;
    __syncthreads();
    if (row == 0) {
#pragma unroll
        for (int i = 1; i < 8; i++) { s += ss[i][lane]; q += qs[i][lane]; }
        g_p2s[blockIdx.y * OCn + oc] = s;
        g_p2q[blockIdx.y * OCn + oc] = q;
    }
}

__global__ void k_fin2(const float* __restrict__ g, const float* __restrict__ bb) {
    const int oc = threadIdx.x;
    float s = 0.f, q = 0.f;
#pragma unroll
    for (int i = 0; i < 16; i++) { s += g_p2s[i * OCn + oc]; q += g_p2q[i * OCn + oc]; }
    const float inv = 1.0f / 65536.0f;
    float m = s * inv;
    float var = q * inv - m * m;
    float a = g[oc] * rsqrtf(var + 1e-5f);
    g_a2[oc] = a;
    g_b2[oc] = bb[oc] - m * a;
}

// ============================================================================
// K7: fused BN2-affine + softmax over the 1024 uv channels (contiguous rows)
// ============================================================================
__global__ void __launch_bounds__(128) k_softmax() {
    __shared__ float red[8];
    float* row = g_k + (size_t)blockIdx.x * OCn;
    const int t = threadIdx.x;
    const int lane = t & 31, wid = t >> 5;

    float4 v0 = *reinterpret_cast<float4*>(row + t * 4);
    float4 v1 = *reinterpret_cast<float4*>(row + 512 + t * 4);
    float4 a0 = *reinterpret_cast<const float4*>(g_a2 + t * 4);
    float4 a1 = *reinterpret_cast<const float4*>(g_a2 + 512 + t * 4);
    float4 b0 = *reinterpret_cast<const float4*>(g_b2 + t * 4);
    float4 b1 = *reinterpret_cast<const float4*>(g_b2 + 512 + t * 4);

    float z[8];
    z[0] = a0.x * v0.x + b0.x; z[1] = a0.y * v0.y + b0.y;
    z[2] = a0.z * v0.z + b0.z; z[3] = a0.w * v0.w + b0.w;
    z[4] = a1.x * v1.x + b1.x; z[5] = a1.y * v1.y + b1.y;
    z[6] = a1.z * v1.z + b1.z; z[7] = a1.w * v1.w + b1.w;

    float m = z[0];
#pragma unroll
    for (int i = 1; i < 8; i++) m = fmaxf(m, z[i]);
#pragma unroll
    for (int o = 16; o > 0; o >>= 1) m = fmaxf(m, __shfl_xor_sync(0xffffffffu, m, o));
    if (lane == 0) red[wid] = m;
    __syncthreads();
    m = fmaxf(fmaxf(red[0], red[1]), fmaxf(red[2], red[3]));

    float s = 0.f;
#pragma unroll
    for (int i = 0; i < 8; i++) { z[i] = __expf(z[i] - m); s += z[i]; }
#pragma unroll
    for (int o = 16; o > 0; o >>= 1) s += __shfl_xor_sync(0xffffffffu, s, o);
    if (lane == 0) red[4 + wid] = s;
    __syncthreads();
    s = (red[4] + red[5]) + (red[6] + red[7]);
    float inv = 1.0f / s;

    v0 = make_float4(z[0] * inv, z[1] * inv, z[2] * inv, z[3] * inv);
    v1 = make_float4(z[4] * inv, z[5] * inv, z[6] * inv, z[7] * inv);
    *reinterpret_cast<float4*>(row + t * 4) = v0;
    *reinterpret_cast<float4*>(row + 512 + t * 4) = v1;
}

// ============================================================================
// K8: final einsum GEMM per batch:
//   out[b][ij][c] = sum_uv kmap[b][ij][uv] * x[b][c][uv]
// A = g_k rows (contiguous), B = x transposed via smem. Output buffer IS
// y[b,i,j,c] row-major (the reference does a raw reshape).
// ============================================================================
__global__ void __launch_bounds__(256, 2)
k_final(const float* __restrict__ x, float* __restrict__ out) {
    __shared__ __align__(16) float As[16 * 130];  // [kk][ij]
    __shared__ __align__(16) float Bs[16 * 130];  // [kk][c]
    const int tid = threadIdx.x;
    const int cb = blockIdx.x * 128, ijb = blockIdx.y * 128, b = blockIdx.z;
    const int tx = tid & 15, ty = tid >> 4;
    const int ij0 = tx * 8, c0 = ty * 8;

    u64 acc[8][4];
#pragma unroll
    for (int p = 0; p < 8; p++)
#pragma unroll
        for (int q = 0; q < 4; q++) acc[p][q] = 0ull;

    const float* kb = g_k + (size_t)b * PXn * OCn;
    const float* xb = x + (size_t)b * Cn * PXn;

#pragma unroll 1
    for (int u0 = 0; u0 < OCn; u0 += 16) {
        __syncthreads();
#pragma unroll
        for (int it = 0; it < 8; ++it) {
            int idx = tid + it * 256;
            int kk = idx & 15, ij = idx >> 4;
            As[kk * 130 + ij] = kb[(size_t)(ijb + ij) * OCn + u0 + kk];
        }
#pragma unroll
        for (int it = 0; it < 8; ++it) {
            int idx = tid + it * 256;
            int kk = idx & 15, c = idx >> 4;
            Bs[kk * 130 + c] = xb[(size_t)(cb + c) * PXn + u0 + kk];
        }
        __syncthreads();
#pragma unroll
        for (int kk = 0; kk < 16; kk++) {
            u64 wp[4];
#pragma unroll
            for (int q = 0; q < 4; q++)
                wp[q] = *reinterpret_cast<const u64*>(&Bs[kk * 130 + c0 + 2 * q]);
#pragma unroll
            for (int p = 0; p < 8; p++) {
                float av = As[kk * 130 + ij0 + p];
                u64 xx = pack2(av, av);
#pragma unroll
                for (int q = 0; q < 4; q++) acc[p][q] = fma2(xx, wp[q], acc[p][q]);
            }
        }
    }

    float* ob = out + (size_t)b * PXn * Cn;
#pragma unroll
    for (int p = 0; p < 8; p++) {
        int ij = ijb + ij0 + p;
#pragma unroll
        for (int q = 0; q < 4; q++) {
            float2 v = unpack2(acc[p][q]);
            *reinterpret_cast<float2*>(&ob[(size_t)ij * Cn + cb + c0 + 2 * q]) = v;
        }
    }
}

// ============================================================================
extern "C" void kernel_launch(void* const* d_in, const int* in_sizes, int n_in,
                              void* d_out, int out_size) {
    (void)in_sizes; (void)n_in; (void)out_size;
    const float* x   = (const float*)d_in[0];
    const float* w1  = (const float*)d_in[1];
    const float* cb1 = (const float*)d_in[2];
    const float* g1  = (const float*)d_in[3];
    const float* bb1 = (const float*)d_in[4];
    const float* w2  = (const float*)d_in[5];
    const float* cb2 = (const float*)d_in[6];
    const float* g2  = (const float*)d_in[7];
    const float* bb2 = (const float*)d_in[8];
    float* out = (float*)d_out;

    k_conv1  <<<dim3(4, 4, Bn), 256>>>(x, w1, cb1);
    k_stats1 <<<dim3(C1n, 8), 256>>>();
    k_fin1   <<<1, C1n>>>(g1, bb1);
    k_conv2  <<<dim3(8, 8, Bn), 256>>>(w2, cb2);
    k_stats2 <<<dim3(32, 16), 256>>>();
    k_fin2   <<<1, OCn>>>(g2, bb2);
    k_softmax<<<Bn * PXn, 128>>>();
    k_final  <<<dim3(2, 8, Bn), 256>>>(x, out);
}

// round 12
// speedup vs baseline: 1.8721x; 1.8719x over previous
#include <cuda_runtime.h>
#include <cuda_fp16.h>

typedef unsigned long long u64;
typedef unsigned int u32;

#define Bn   64
#define Cn   256
#define HWn  32
#define PXn  1024
#define C1n  256
#define OCn  1024

// ---------------- scratch (device globals; no allocation allowed) ----------
__device__ __align__(16) float g_h[Bn * C1n * PXn];          // 67 MB  [b][c1][px]
__device__ __align__(16) float g_k[(size_t)Bn * PXn * OCn];  // 268 MB [b][ij][uv]
__device__ float g_p1s[8 * C1n],  g_p1q[8 * C1n];
__device__ float g_a1[C1n], g_b1[C1n];
__device__ float g_p2s[16 * OCn], g_p2q[16 * OCn];
__device__ __align__(16) float g_a2[OCn];
__device__ __align__(16) float g_b2[OCn];
// fp16 hi/lo split operands for conv1 tensor-core path
__device__ __align__(16) __half g_wt[2][49 * 256 * 256];                 // [prec][tap][oc][c]
__device__ __align__(16) __half g_xp[2][(size_t)Bn * 4 * 256 * 256];     // [prec][b][par][c][px]

// ---------------- packed fp32x2 helpers ------------------------------------
__device__ __forceinline__ u64 pack2(float lo, float hi) {
    u64 r; asm("mov.b64 %0, {%1, %2};" : "=l"(r) : "f"(lo), "f"(hi)); return r;
}
__device__ __forceinline__ u64 fma2(u64 a, u64 b, u64 c) {
    u64 d; asm("fma.rn.f32x2 %0, %1, %2, %3;" : "=l"(d) : "l"(a), "l"(b), "l"(c)); return d;
}
__device__ __forceinline__ float2 unpack2(u64 v) {
    float2 f; asm("mov.b64 {%0, %1}, %2;" : "=f"(f.x), "=f"(f.y) : "l"(v)); return f;
}

__device__ __forceinline__ u32 smem_u32(const void* p) {
    return (u32)__cvta_generic_to_shared(p);
}

#define LDSM4(R0,R1,R2,R3,A) \
  asm volatile("ldmatrix.sync.aligned.m8n8.x4.shared.b16 {%0,%1,%2,%3}, [%4];" \
    : "=r"(R0),"=r"(R1),"=r"(R2),"=r"(R3) : "r"(A))

#define MMA16816(C,A0,A1,A2,A3,B0,B1) \
  asm volatile("mma.sync.aligned.m16n8k16.row.col.f32.f16.f16.f32 " \
    "{%0,%1,%2,%3},{%4,%5,%6,%7},{%8,%9},{%0,%1,%2,%3};" \
    : "+f"(C[0]),"+f"(C[1]),"+f"(C[2]),"+f"(C[3]) \
    : "r"(A0),"r"(A1),"r"(A2),"r"(A3),"r"(B0),"r"(B1))

#define CP16(DST,SRC) \
  asm volatile("cp.async.cg.shared.global [%0], [%1], 16;" :: "r"(DST), "l"(SRC))
#define CPCOMMIT() asm volatile("cp.async.commit_group;")
#define CPWAIT0()  asm volatile("cp.async.wait_group 0;" ::: "memory")

// ============================================================================
// P1: split conv1 weights into fp16 hi/lo, layout [prec][tap][oc][c]
// ============================================================================
__global__ void k_prep_w(const float* __restrict__ w1) {
    const int tap = blockIdx.x;
    for (int i = threadIdx.x; i < 65536; i += 256) {      // i = oc*256 + c
        float v = w1[(size_t)i * 49 + tap];
        __half h = __float2half(v);
        __half l = __float2half(v - __half2float(h));
        g_wt[0][(size_t)tap * 65536 + i] = h;
        g_wt[1][(size_t)tap * 65536 + i] = l;
    }
}

// ============================================================================
// P2: split x into fp16 hi/lo parity subgrids, layout [prec][b][par][c][px256]
// ============================================================================
__global__ void k_prep_x(const float* __restrict__ x) {
    const int c = blockIdx.x, b = blockIdx.y;
    const int px = threadIdx.x;                     // 0..255
    const int si = px >> 4, sj = px & 15;
    const float* xc = x + ((size_t)b * Cn + c) * PXn;
#pragma unroll
    for (int par = 0; par < 4; ++par) {
        float v = xc[(2 * si + (par >> 1)) * HWn + 2 * sj + (par & 1)];
        __half h = __float2half(v);
        __half l = __float2half(v - __half2float(h));
        size_t o = (((size_t)b * 4 + par) * 256 + c) * 256 + px;
        g_xp[0][o] = h;
        g_xp[1][o] = l;
    }
}

// ============================================================================
// K1: conv1 7x7 dilation-2 pad-6 via 4 parity subgrids, tensor cores.
// Block: 64 oc x one (b, parity) subgrid (256 px). 8 warps; each warp owns
// 2 subgrid rows (m-tiles of 16 px) x 8 oc-tiles. fp16 hi/lo split: 3 MMAs
// (hi*hi + hi*lo + lo*hi) per tile per k-step, fp32 accumulators.
// ============================================================================
__global__ void __launch_bounds__(256, 1)
k_conv1(const float* __restrict__ cb1) {
    __shared__ __align__(16) __half xs[2][484 * 16];     // [prec][halo pix 22x22][c16]
    __shared__ __align__(16) __half ws[2][2][64 * 24];   // [buf][prec][oc][c16 pad24]

    const int tid = threadIdx.x;
    const int lane = tid & 31, wid = tid >> 5;
    const int ocb = blockIdx.x * 64;
    const int par = blockIdx.y;
    const int pi = par >> 1, pj = par & 1;
    const int b = blockIdx.z;

    // zero xs (halo stays zero; interior rewritten per c-chunk)
    for (int i = tid; i < 484 * 16; i += 256) {
        xs[0][i] = __float2half(0.f);
        xs[1][i] = __float2half(0.f);
    }

    float acc[2][8][4];
#pragma unroll
    for (int m = 0; m < 2; m++)
#pragma unroll
        for (int n = 0; n < 8; n++)
#pragma unroll
            for (int q = 0; q < 4; q++) acc[m][n][q] = 0.f;

    // per-thread weight staging (one 16B cp.async each: 2 prec x 64 oc x 2 halves)
    const int sprec = tid >> 7;
    const int soc   = (tid & 127) >> 1;
    const int shalf = tid & 1;
    const __half* wsrc0 = g_wt[sprec] + (size_t)(ocb + soc) * 256 + shalf * 8;
    u32 wdst[2];
    wdst[0] = smem_u32(&ws[0][sprec][soc * 24 + shalf * 8]);
    wdst[1] = smem_u32(&ws[1][sprec][soc * 24 + shalf * 8]);

    const __half* xp0 = g_xp[0] + (((size_t)b * 4 + par) * 256) * 256;
    const __half* xp1 = g_xp[1] + (((size_t)b * 4 + par) * 256) * 256;

    const int lrow = lane & 15;
    const int lkof = (lane >> 4) * 8;
    const u32 xsa = smem_u32(xs);
    const u32 wsa = smem_u32(ws);

    for (int cc = 0; cc < 16; ++cc) {
        const int c0 = cc * 16;
        __syncthreads();   // previous chunk's reads done before overwriting xs
        for (int i = tid; i < 4096; i += 256) {
            int c = i >> 8, px = i & 255;
            int si = px >> 4, sj = px & 15;
            int d = ((si + 3) * 22 + (sj + 3)) * 16 + c;
            xs[0][d] = xp0[(size_t)(c0 + c) * 256 + px];
            xs[1][d] = xp1[(size_t)(c0 + c) * 256 + px];
        }
        const __half* wsrc = wsrc0 + c0;
        CP16(wdst[0], wsrc);       // stage tap 0 into buf 0
        CPCOMMIT();

        int buf = 0, kh = 0, kw = 0;
        for (int tap = 0; tap < 49; ++tap) {
            CPWAIT0();             // stage(tap) complete
            __syncthreads();       // visible to all; all done with other buffer
            if (tap < 48) {
                CP16(wdst[buf ^ 1], wsrc + (size_t)(tap + 1) * 65536);
                CPCOMMIT();
            }
            // B fragments: 4 ldmatrix.x4 per precision cover 64 oc x 16 c
            u32 bh[4][4], bl[4][4];
            const u32 wbase = wsa + (u32)(buf * (2 * 64 * 24 * 2));
#pragma unroll
            for (int p = 0; p < 4; ++p) {
                u32 a0 = wbase + (u32)(((p * 16 + lrow) * 24 + lkof) * 2);
                LDSM4(bh[p][0], bh[p][1], bh[p][2], bh[p][3], a0);
                LDSM4(bl[p][0], bl[p][1], bl[p][2], bl[p][3], a0 + (u32)(64 * 24 * 2));
            }
#pragma unroll
            for (int mt = 0; mt < 2; ++mt) {
                int pixr = (2 * wid + mt + kh) * 22 + lrow + kw;
                u32 aadr = xsa + (u32)((pixr * 16 + lkof) * 2);
                u32 ah[4], al[4];
                LDSM4(ah[0], ah[1], ah[2], ah[3], aadr);
                LDSM4(al[0], al[1], al[2], al[3], aadr + (u32)(484 * 16 * 2));
#pragma unroll
                for (int nt = 0; nt < 8; ++nt) {
                    int p = nt >> 1, o = nt & 1;
                    MMA16816(acc[mt][nt], ah[0], ah[1], ah[2], ah[3], bh[p][o], bh[p][o + 2]);
                }
#pragma unroll
                for (int nt = 0; nt < 8; ++nt) {
                    int p = nt >> 1, o = nt & 1;
                    MMA16816(acc[mt][nt], ah[0], ah[1], ah[2], ah[3], bl[p][o], bl[p][o + 2]);
                }
#pragma unroll
                for (int nt = 0; nt < 8; ++nt) {
                    int p = nt >> 1, o = nt & 1;
                    MMA16816(acc[mt][nt], al[0], al[1], al[2], al[3], bh[p][o], bh[p][o + 2]);
                }
            }
            buf ^= 1;
            if (++kw == 7) { kw = 0; ++kh; }
        }
    }

    // epilogue: + conv1 bias, scatter into g_h[b][oc][fi*32+fj]
    const int sj0 = lane >> 2;
    const int ocl = 2 * (lane & 3);
    float* hb = g_h + (size_t)b * C1n * PXn;
#pragma unroll
    for (int mt = 0; mt < 2; ++mt) {
        int si = 2 * wid + mt;
        int fi = 2 * si + pi;
#pragma unroll
        for (int nt = 0; nt < 8; ++nt) {
            int oc = ocb + nt * 8 + ocl;
            float bz0 = cb1[oc], bz1 = cb1[oc + 1];
            int fja = 2 * sj0 + pj, fjb = 2 * (sj0 + 8) + pj;
            hb[(size_t)oc * PXn + fi * HWn + fja]       = acc[mt][nt][0] + bz0;
            hb[(size_t)(oc + 1) * PXn + fi * HWn + fja] = acc[mt][nt][1] + bz1;
            hb[(size_t)oc * PXn + fi * HWn + fjb]       = acc[mt][nt][2] + bz0;
            hb[(size_t)(oc + 1) * PXn + fi * HWn + fjb] = acc[mt][nt][3] + bz1;
        }
    }
}

// ============================================================================
// K2/K3: BN1 batch stats (deterministic two-stage reduction) + finalize
// ============================================================================
__global__ void __launch_bounds__(256) k_stats1() {
    const int c = blockIdx.x;
    const int b0 = blockIdx.y * 8;
    float s = 0.f, q = 0.f;
    for (int b = b0; b < b0 + 8; ++b) {
        const float* hp = g_h + ((size_t)b * C1n + c) * PXn;
        for (int px = threadIdx.x; px < PXn; px += 256) {
            float v = hp[px]; s += v; q += v * v;
        }
    }
    __shared__ float ss[256], qs[256];
    ss[threadIdx.x] = s; qs[threadIdx.x] = q;
    __syncthreads();
    for (int o = 128; o > 0; o >>= 1) {
        if (threadIdx.x < o) {
            ss[threadIdx.x] += ss[threadIdx.x + o];
            qs[threadIdx.x] += qs[threadIdx.x + o];
        }
        __syncthreads();
    }
    if (threadIdx.x == 0) {
        g_p1s[blockIdx.y * C1n + c] = ss[0];
        g_p1q[blockIdx.y * C1n + c] = qs[0];
    }
}

__global__ void k_fin1(const float* __restrict__ g, const float* __restrict__ bb) {
    const int c = threadIdx.x;
    float s = 0.f, q = 0.f;
#pragma unroll
    for (int i = 0; i < 8; i++) { s += g_p1s[i * C1n + c]; q += g_p1q[i * C1n + c]; }
    const float inv = 1.0f / 65536.0f;
    float m = s * inv;
    float var = q * inv - m * m;
    float a = g[c] * rsqrtf(var + 1e-5f);
    g_a1[c] = a;
    g_b1[c] = bb[c] - m * a;
}

// ============================================================================
// K4: conv2 1x1 GEMM per batch (FFMA2 path)
// ============================================================================
__global__ void __launch_bounds__(256, 2)
k_conv2(const float* __restrict__ w2, const float* __restrict__ cb2) {
    __shared__ __align__(16) float As[16 * 130];
    __shared__ __align__(16) float Bs[16 * 128];
    const int tid = threadIdx.x;
    const int pxb = blockIdx.x * 128, ocb = blockIdx.y * 128, b = blockIdx.z;
    const int tx = tid & 15, ty = tid >> 4;
    const int px0 = tx * 8, oc0 = ty * 8;

    u64 acc[8][4];
#pragma unroll
    for (int p = 0; p < 8; p++)
#pragma unroll
        for (int q = 0; q < 4; q++) acc[p][q] = 0ull;

#pragma unroll 1
    for (int k0 = 0; k0 < C1n; k0 += 16) {
        __syncthreads();
#pragma unroll
        for (int it = 0; it < 8; ++it) {
            int idx = tid + it * 256;
            int kk = idx & 15, oc = idx >> 4;
            As[kk * 130 + oc] = w2[(size_t)(ocb + oc) * C1n + k0 + kk];
        }
#pragma unroll
        for (int it = 0; it < 8; ++it) {
            int idx = tid + it * 256;
            int px = idx & 127, kk = idx >> 7;
            int c = k0 + kk;
            float hv = g_h[((size_t)b * C1n + c) * PXn + pxb + px];
            Bs[kk * 128 + px] = g_a1[c] * hv + g_b1[c];
        }
        __syncthreads();
#pragma unroll
        for (int kk = 0; kk < 16; kk++) {
            float4 bA = *reinterpret_cast<const float4*>(&Bs[kk * 128 + px0]);
            float4 bB = *reinterpret_cast<const float4*>(&Bs[kk * 128 + px0 + 4]);
            u64 wp[4];
#pragma unroll
            for (int q = 0; q < 4; q++)
                wp[q] = *reinterpret_cast<const u64*>(&As[kk * 130 + oc0 + 2 * q]);
            float bv[8] = {bA.x, bA.y, bA.z, bA.w, bB.x, bB.y, bB.z, bB.w};
#pragma unroll
            for (int p = 0; p < 8; p++) {
                u64 xx = pack2(bv[p], bv[p]);
#pragma unroll
                for (int q = 0; q < 4; q++) acc[p][q] = fma2(xx, wp[q], acc[p][q]);
            }
        }
    }

    float* kb = g_k + (size_t)b * PXn * OCn;
#pragma unroll
    for (int q = 0; q < 4; q++) {
        int oc = ocb + oc0 + 2 * q;
        float c0v = cb2[oc], c1v = cb2[oc + 1];
#pragma unroll
        for (int p = 0; p < 8; p++) {
            int px = pxb + px0 + p;
            float2 v = unpack2(acc[p][q]);
            float2 o; o.x = v.x + c0v; o.y = v.y + c1v;
            *reinterpret_cast<float2*>(&kb[(size_t)px * OCn + oc]) = o;
        }
    }
}

// ============================================================================
// K5/K6: BN2 stats + finalize
// ============================================================================
__global__ void __launch_bounds__(256) k_stats2() {
    const int lane = threadIdx.x & 31, row = threadIdx.x >> 5;
    const int oc = blockIdx.x * 32 + lane;
    const int r0 = blockIdx.y * 4096;
    float s = 0.f, q = 0.f;
    for (int r = r0 + row; r < r0 + 4096; r += 8) {
        float v = g_k[(size_t)r * OCn + oc];
        s += v; q += v * v;
    }
    __shared__ float ss[8][33], qs[8][33];
    ss[row][lane] = s; qs[row][lane] = q;
    __syncthreads();
    if (row == 0) {
#pragma unroll
        for (int i = 1; i < 8; i++) { s += ss[i][lane]; q += qs[i][lane]; }
        g_p2s[blockIdx.y * OCn + oc] = s;
        g_p2q[blockIdx.y * OCn + oc] = q;
    }
}

__global__ void k_fin2(const float* __restrict__ g, const float* __restrict__ bb) {
    const int oc = threadIdx.x;
    float s = 0.f, q = 0.f;
#pragma unroll
    for (int i = 0; i < 16; i++) { s += g_p2s[i * OCn + oc]; q += g_p2q[i * OCn + oc]; }
    const float inv = 1.0f / 65536.0f;
    float m = s * inv;
    float var = q * inv - m * m;
    float a = g[oc] * rsqrtf(var + 1e-5f);
    g_a2[oc] = a;
    g_b2[oc] = bb[oc] - m * a;
}

// ============================================================================
// K7: fused BN2-affine + softmax over 1024 uv channels (contiguous rows)
// ============================================================================
__global__ void __launch_bounds__(128) k_softmax() {
    __shared__ float red[8];
    float* row = g_k + (size_t)blockIdx.x * OCn;
    const int t = threadIdx.x;
    const int lane = t & 31, wid = t >> 5;

    float4 v0 = *reinterpret_cast<float4*>(row + t * 4);
    float4 v1 = *reinterpret_cast<float4*>(row + 512 + t * 4);
    float4 a0 = *reinterpret_cast<const float4*>(g_a2 + t * 4);
    float4 a1 = *reinterpret_cast<const float4*>(g_a2 + 512 + t * 4);
    float4 b0 = *reinterpret_cast<const float4*>(g_b2 + t * 4);
    float4 b1 = *reinterpret_cast<const float4*>(g_b2 + 512 + t * 4);

    float z[8];
    z[0] = a0.x * v0.x + b0.x; z[1] = a0.y * v0.y + b0.y;
    z[2] = a0.z * v0.z + b0.z; z[3] = a0.w * v0.w + b0.w;
    z[4] = a1.x * v1.x + b1.x; z[5] = a1.y * v1.y + b1.y;
    z[6] = a1.z * v1.z + b1.z; z[7] = a1.w * v1.w + b1.w;

    float m = z[0];
#pragma unroll
    for (int i = 1; i < 8; i++) m = fmaxf(m, z[i]);
#pragma unroll
    for (int o = 16; o > 0; o >>= 1) m = fmaxf(m, __shfl_xor_sync(0xffffffffu, m, o));
    if (lane == 0) red[wid] = m;
    __syncthreads();
    m = fmaxf(fmaxf(red[0], red[1]), fmaxf(red[2], red[3]));

    float s = 0.f;
#pragma unroll
    for (int i = 0; i < 8; i++) { z[i] = __expf(z[i] - m); s += z[i]; }
#pragma unroll
    for (int o = 16; o > 0; o >>= 1) s += __shfl_xor_sync(0xffffffffu, s, o);
    if (lane == 0) red[4 + wid] = s;
    __syncthreads();
    s = (red[4] + red[5]) + (red[6] + red[7]);
    float inv = 1.0f / s;

    v0 = make_float4(z[0] * inv, z[1] * inv, z[2] * inv, z[3] * inv);
    v1 = make_float4(z[4] * inv, z[5] * inv, z[6] * inv, z[7] * inv);
    *reinterpret_cast<float4*>(row + t * 4) = v0;
    *reinterpret_cast<float4*>(row + 512 + t * 4) = v1;
}

// ============================================================================
// K8: final einsum GEMM per batch (FFMA2 path)
// ============================================================================
__global__ void __launch_bounds__(256, 2)
k_final(const float* __restrict__ x, float* __restrict__ out) {
    __shared__ __align__(16) float As[16 * 130];
    __shared__ __align__(16) float Bs[16 * 130];
    const int tid = threadIdx.x;
    const int cb = blockIdx.x * 128, ijb = blockIdx.y * 128, b = blockIdx.z;
    const int tx = tid & 15, ty = tid >> 4;
    const int ij0 = tx * 8, c0 = ty * 8;

    u64 acc[8][4];
#pragma unroll
    for (int p = 0; p < 8; p++)
#pragma unroll
        for (int q = 0; q < 4; q++) acc[p][q] = 0ull;

    const float* kb = g_k + (size_t)b * PXn * OCn;
    const float* xb = x + (size_t)b * Cn * PXn;

#pragma unroll 1
    for (int u0 = 0; u0 < OCn; u0 += 16) {
        __syncthreads();
#pragma unroll
        for (int it = 0; it < 8; ++it) {
            int idx = tid + it * 256;
            int kk = idx & 15, ij = idx >> 4;
            As[kk * 130 + ij] = kb[(size_t)(ijb + ij) * OCn + u0 + kk];
        }
#pragma unroll
        for (int it = 0; it < 8; ++it) {
            int idx = tid + it * 256;
            int kk = idx & 15, c = idx >> 4;
            Bs[kk * 130 + c] = xb[(size_t)(cb + c) * PXn + u0 + kk];
        }
        __syncthreads();
#pragma unroll
        for (int kk = 0; kk < 16; kk++) {
            u64 wp[4];
#pragma unroll
            for (int q = 0; q < 4; q++)
                wp[q] = *reinterpret_cast<const u64*>(&Bs[kk * 130 + c0 + 2 * q]);
#pragma unroll
            for (int p = 0; p < 8; p++) {
                float av = As[kk * 130 + ij0 + p];
                u64 xx = pack2(av, av);
#pragma unroll
                for (int q = 0; q < 4; q++) acc[p][q] = fma2(xx, wp[q], acc[p][q]);
            }
        }
    }

    float* ob = out + (size_t)b * PXn * Cn;
#pragma unroll
    for (int p = 0; p < 8; p++) {
        int ij = ijb + ij0 + p;
#pragma unroll
        for (int q = 0; q < 4; q++) {
            float2 v = unpack2(acc[p][q]);
            *reinterpret_cast<float2*>(&ob[(size_t)ij * Cn + cb + c0 + 2 * q]) = v;
        }
    }
}

// ============================================================================
extern "C" void kernel_launch(void* const* d_in, const int* in_sizes, int n_in,
                              void* d_out, int out_size) {
    (void)in_sizes; (void)n_in; (void)out_size;
    const float* x   = (const float*)d_in[0];
    const float* w1  = (const float*)d_in[1];
    const float* cb1 = (const float*)d_in[2];
    const float* g1  = (const float*)d_in[3];
    const float* bb1 = (const float*)d_in[4];
    const float* w2  = (const float*)d_in[5];
    const float* cb2 = (const float*)d_in[6];
    const float* g2  = (const float*)d_in[7];
    const float* bb2 = (const float*)d_in[8];
    float* out = (float*)d_out;

    k_prep_w <<<49, 256>>>(w1);
    k_prep_x <<<dim3(Cn, Bn), 256>>>(x);
    k_conv1  <<<dim3(4, 4, Bn), 256>>>(cb1);
    k_stats1 <<<dim3(C1n, 8), 256>>>();
    k_fin1   <<<1, C1n>>>(g1, bb1);
    k_conv2  <<<dim3(8, 8, Bn), 256>>>(w2, cb2);
    k_stats2 <<<dim3(32, 16), 256>>>();
    k_fin2   <<<1, OCn>>>(g2, bb2);
    k_softmax<<<Bn * PXn, 128>>>();
    k_final  <<<dim3(2, 8, Bn), 256>>>(x, out);
}

// round 13
// speedup vs baseline: 2.2439x; 1.1986x over previous
#include <cuda_runtime.h>
#include <cuda_fp16.h>

typedef unsigned long long u64;
typedef unsigned int u32;

#define Bn   64
#define Cn   256
#define HWn  32
#define PXn  1024
#define C1n  256
#define OCn  1024

// ---------------- scratch (device globals; no allocation allowed) ----------
__device__ __align__(16) float g_h[Bn * C1n * PXn];          // 67 MB  [b][c1][px]
__device__ __align__(16) float g_k[(size_t)Bn * PXn * OCn];  // 268 MB [b][ij][uv] (pre-BN2 z)
__device__ float g_p1s[8 * C1n],  g_p1q[8 * C1n];
__device__ float g_a1[C1n], g_b1[C1n];
__device__ float g_p2s[16 * OCn], g_p2q[16 * OCn];
__device__ __align__(16) float g_a2[OCn];
__device__ __align__(16) float g_b2[OCn];
// fp16 hi/lo split operands
__device__ __align__(16) __half g_wt[2][49 * 256 * 256];                 // conv1 W [prec][tap][oc][c]
__device__ __align__(16) __half g_xp[2][(size_t)Bn * 4 * 256 * 256];     // conv1 x [prec][b][par][c][px]
__device__ __align__(16) __half g_w2h[2][OCn * C1n];                     // conv2 W [prec][oc][c]
__device__ __align__(16) __half g_xn[2][(size_t)Bn * Cn * PXn];          // final x [prec][b][c][uv]
__device__ __align__(16) __half g_kh[2][(size_t)Bn * PXn * OCn];         // softmax out [prec][b][ij][uv]

__device__ __forceinline__ u32 smem_u32(const void* p) {
    return (u32)__cvta_generic_to_shared(p);
}

#define LDSM4(R0,R1,R2,R3,A) \
  asm volatile("ldmatrix.sync.aligned.m8n8.x4.shared.b16 {%0,%1,%2,%3}, [%4];" \
    : "=r"(R0),"=r"(R1),"=r"(R2),"=r"(R3) : "r"(A))

#define LDSM4T(R0,R1,R2,R3,A) \
  asm volatile("ldmatrix.sync.aligned.m8n8.x4.trans.shared.b16 {%0,%1,%2,%3}, [%4];" \
    : "=r"(R0),"=r"(R1),"=r"(R2),"=r"(R3) : "r"(A))

#define MMA16816(C,A0,A1,A2,A3,B0,B1) \
  asm volatile("mma.sync.aligned.m16n8k16.row.col.f32.f16.f16.f32 " \
    "{%0,%1,%2,%3},{%4,%5,%6,%7},{%8,%9},{%0,%1,%2,%3};" \
    : "+f"(C[0]),"+f"(C[1]),"+f"(C[2]),"+f"(C[3]) \
    : "r"(A0),"r"(A1),"r"(A2),"r"(A3),"r"(B0),"r"(B1))

#define CP16(DST,SRC) \
  asm volatile("cp.async.cg.shared.global [%0], [%1], 16;" :: "r"(DST), "l"(SRC))
#define CPCOMMIT() asm volatile("cp.async.commit_group;")
#define CPWAIT0()  asm volatile("cp.async.wait_group 0;" ::: "memory")

// ============================================================================
// P1: split conv1 weights into fp16 hi/lo, layout [prec][tap][oc][c]
// ============================================================================
__global__ void k_prep_w(const float* __restrict__ w1) {
    const int tap = blockIdx.x;
    for (int i = threadIdx.x; i < 65536; i += 256) {      // i = oc*256 + c
        float v = w1[(size_t)i * 49 + tap];
        __half h = __float2half(v);
        __half l = __float2half(v - __half2float(h));
        g_wt[0][(size_t)tap * 65536 + i] = h;
        g_wt[1][(size_t)tap * 65536 + i] = l;
    }
}

// ============================================================================
// P1b: split conv2 weights into fp16 hi/lo, layout [prec][oc][c]
// ============================================================================
__global__ void k_prep_w2(const float* __restrict__ w2) {
    int i = blockIdx.x * 1024 + threadIdx.x;
#pragma unroll
    for (int r = 0; r < 4; ++r, i += 256) {
        float v = w2[i];
        __half h = __float2half(v);
        g_w2h[0][i] = h;
        g_w2h[1][i] = __float2half(v - __half2float(h));
    }
}

// ============================================================================
// P2: split x into fp16 hi/lo: parity subgrids (conv1) + native [c][uv] (final)
// ============================================================================
__global__ void k_prep_x(const float* __restrict__ x) {
    const int c = blockIdx.x, b = blockIdx.y;
    const int px = threadIdx.x;                     // 0..255
    const int si = px >> 4, sj = px & 15;
    const float* xc = x + ((size_t)b * Cn + c) * PXn;
#pragma unroll
    for (int par = 0; par < 4; ++par) {
        int fi = 2 * si + (par >> 1), fj = 2 * sj + (par & 1);
        float v = xc[fi * HWn + fj];
        __half h = __float2half(v);
        __half l = __float2half(v - __half2float(h));
        size_t o = (((size_t)b * 4 + par) * 256 + c) * 256 + px;
        g_xp[0][o] = h;
        g_xp[1][o] = l;
        size_t on = ((size_t)b * Cn + c) * PXn + fi * HWn + fj;
        g_xn[0][on] = h;
        g_xn[1][on] = l;
    }
}

// ============================================================================
// K1: conv1 7x7 dilation-2 pad-6 via 4 parity subgrids, tensor cores.
// (unchanged from R7 — validated)
// ============================================================================
__global__ void __launch_bounds__(256, 1)
k_conv1(const float* __restrict__ cb1) {
    __shared__ __align__(16) __half xs[2][484 * 16];     // [prec][halo pix 22x22][c16]
    __shared__ __align__(16) __half ws[2][2][64 * 24];   // [buf][prec][oc][c16 pad24]

    const int tid = threadIdx.x;
    const int lane = tid & 31, wid = tid >> 5;
    const int ocb = blockIdx.x * 64;
    const int par = blockIdx.y;
    const int pi = par >> 1, pj = par & 1;
    const int b = blockIdx.z;

    for (int i = tid; i < 484 * 16; i += 256) {
        xs[0][i] = __float2half(0.f);
        xs[1][i] = __float2half(0.f);
    }

    float acc[2][8][4];
#pragma unroll
    for (int m = 0; m < 2; m++)
#pragma unroll
        for (int n = 0; n < 8; n++)
#pragma unroll
            for (int q = 0; q < 4; q++) acc[m][n][q] = 0.f;

    const int sprec = tid >> 7;
    const int soc   = (tid & 127) >> 1;
    const int shalf = tid & 1;
    const __half* wsrc0 = g_wt[sprec] + (size_t)(ocb + soc) * 256 + shalf * 8;
    u32 wdst[2];
    wdst[0] = smem_u32(&ws[0][sprec][soc * 24 + shalf * 8]);
    wdst[1] = smem_u32(&ws[1][sprec][soc * 24 + shalf * 8]);

    const __half* xp0 = g_xp[0] + (((size_t)b * 4 + par) * 256) * 256;
    const __half* xp1 = g_xp[1] + (((size_t)b * 4 + par) * 256) * 256;

    const int lrow = lane & 15;
    const int lkof = (lane >> 4) * 8;
    const u32 xsa = smem_u32(xs);
    const u32 wsa = smem_u32(ws);

    for (int cc = 0; cc < 16; ++cc) {
        const int c0 = cc * 16;
        __syncthreads();
        for (int i = tid; i < 4096; i += 256) {
            int c = i >> 8, px = i & 255;
            int si = px >> 4, sj = px & 15;
            int d = ((si + 3) * 22 + (sj + 3)) * 16 + c;
            xs[0][d] = xp0[(size_t)(c0 + c) * 256 + px];
            xs[1][d] = xp1[(size_t)(c0 + c) * 256 + px];
        }
        const __half* wsrc = wsrc0 + c0;
        CP16(wdst[0], wsrc);
        CPCOMMIT();

        int buf = 0, kh = 0, kw = 0;
        for (int tap = 0; tap < 49; ++tap) {
            CPWAIT0();
            __syncthreads();
            if (tap < 48) {
                CP16(wdst[buf ^ 1], wsrc + (size_t)(tap + 1) * 65536);
                CPCOMMIT();
            }
            u32 bh[4][4], bl[4][4];
            const u32 wbase = wsa + (u32)(buf * (2 * 64 * 24 * 2));
#pragma unroll
            for (int p = 0; p < 4; ++p) {
                u32 a0 = wbase + (u32)(((p * 16 + lrow) * 24 + lkof) * 2);
                LDSM4(bh[p][0], bh[p][1], bh[p][2], bh[p][3], a0);
                LDSM4(bl[p][0], bl[p][1], bl[p][2], bl[p][3], a0 + (u32)(64 * 24 * 2));
            }
#pragma unroll
            for (int mt = 0; mt < 2; ++mt) {
                int pixr = (2 * wid + mt + kh) * 22 + lrow + kw;
                u32 aadr = xsa + (u32)((pixr * 16 + lkof) * 2);
                u32 ah[4], al[4];
                LDSM4(ah[0], ah[1], ah[2], ah[3], aadr);
                LDSM4(al[0], al[1], al[2], al[3], aadr + (u32)(484 * 16 * 2));
#pragma unroll
                for (int nt = 0; nt < 8; ++nt) {
                    int p = nt >> 1, o = nt & 1;
                    MMA16816(acc[mt][nt], ah[0], ah[1], ah[2], ah[3], bh[p][o], bh[p][o + 2]);
                }
#pragma unroll
                for (int nt = 0; nt < 8; ++nt) {
                    int p = nt >> 1, o = nt & 1;
                    MMA16816(acc[mt][nt], ah[0], ah[1], ah[2], ah[3], bl[p][o], bl[p][o + 2]);
                }
#pragma unroll
                for (int nt = 0; nt < 8; ++nt) {
                    int p = nt >> 1, o = nt & 1;
                    MMA16816(acc[mt][nt], al[0], al[1], al[2], al[3], bh[p][o], bh[p][o + 2]);
                }
            }
            buf ^= 1;
            if (++kw == 7) { kw = 0; ++kh; }
        }
    }

    const int sj0 = lane >> 2;
    const int ocl = 2 * (lane & 3);
    float* hb = g_h + (size_t)b * C1n * PXn;
#pragma unroll
    for (int mt = 0; mt < 2; ++mt) {
        int si = 2 * wid + mt;
        int fi = 2 * si + pi;
#pragma unroll
        for (int nt = 0; nt < 8; ++nt) {
            int oc = ocb + nt * 8 + ocl;
            float bz0 = cb1[oc], bz1 = cb1[oc + 1];
            int fja = 2 * sj0 + pj, fjb = 2 * (sj0 + 8) + pj;
            hb[(size_t)oc * PXn + fi * HWn + fja]       = acc[mt][nt][0] + bz0;
            hb[(size_t)(oc + 1) * PXn + fi * HWn + fja] = acc[mt][nt][1] + bz1;
            hb[(size_t)oc * PXn + fi * HWn + fjb]       = acc[mt][nt][2] + bz0;
            hb[(size_t)(oc + 1) * PXn + fi * HWn + fjb] = acc[mt][nt][3] + bz1;
        }
    }
}

// ============================================================================
// K2/K3: BN1 batch stats + finalize
// ============================================================================
__global__ void __launch_bounds__(256) k_stats1() {
    const int c = blockIdx.x;
    const int b0 = blockIdx.y * 8;
    float s = 0.f, q = 0.f;
    for (int b = b0; b < b0 + 8; ++b) {
        const float* hp = g_h + ((size_t)b * C1n + c) * PXn;
        for (int px = threadIdx.x; px < PXn; px += 256) {
            float v = hp[px]; s += v; q += v * v;
        }
    }
    __shared__ float ss[256], qs[256];
    ss[threadIdx.x] = s; qs[threadIdx.x] = q;
    __syncthreads();
    for (int o = 128; o > 0; o >>= 1) {
        if (threadIdx.x < o) {
            ss[threadIdx.x] += ss[threadIdx.x + o];
            qs[threadIdx.x] += qs[threadIdx.x + o];
        }
        __syncthreads();
    }
    if (threadIdx.x == 0) {
        g_p1s[blockIdx.y * C1n + c] = ss[0];
        g_p1q[blockIdx.y * C1n + c] = qs[0];
    }
}

__global__ void k_fin1(const float* __restrict__ g, const float* __restrict__ bb) {
    const int c = threadIdx.x;
    float s = 0.f, q = 0.f;
#pragma unroll
    for (int i = 0; i < 8; i++) { s += g_p1s[i * C1n + c]; q += g_p1q[i * C1n + c]; }
    const float inv = 1.0f / 65536.0f;
    float m = s * inv;
    float var = q * inv - m * m;
    float a = g[c] * rsqrtf(var + 1e-5f);
    g_a1[c] = a;
    g_b1[c] = bb[c] - m * a;
}

// ============================================================================
// K4: conv2 1x1 GEMM per batch, tensor cores (fp16 hi/lo split).
//   z[px][oc] = sum_c W2[oc][c] * (a1*h+b1)[c][px] + cb2[oc]
// A = affine-h^T via ldmatrix.trans from [c][px] smem; B = W2 rows [oc][c].
// Block: 128 px x 128 oc. 8 warps (4m x 2n), warp: 32 px x 64 oc.
// ============================================================================
__global__ void __launch_bounds__(256, 2)
k_conv2(const float* __restrict__ cb2) {
    __shared__ __align__(16) __half As[2][32][136];   // [prec][k=c][m=px pad136]
    __shared__ __align__(16) __half Bs[2][128][40];   // [prec][n=oc][k=c pad40]
    const int tid = threadIdx.x;
    const int lane = tid & 31, wid = tid >> 5;
    const int pxb = blockIdx.x * 128, ocb = blockIdx.y * 128, b = blockIdx.z;
    const int wm = wid & 3, wn = wid >> 2;

    float acc[2][8][4];
#pragma unroll
    for (int m = 0; m < 2; m++)
#pragma unroll
        for (int n = 0; n < 8; n++)
#pragma unroll
            for (int q = 0; q < 4; q++) acc[m][n][q] = 0.f;

    // trans-ldmatrix A addressing (fragments of [m][k] from [k][m] storage)
    const int arow = (lane & 7) + ((lane >> 4) & 1) * 8;
    const int acol = ((lane >> 3) & 1) * 8 + wm * 32;
    // non-trans B addressing
    const int lrow = lane & 15, lkof = (lane >> 4) * 8;

#pragma unroll 1
    for (int k0 = 0; k0 < C1n; k0 += 32) {
        __syncthreads();
#pragma unroll
        for (int it = 0; it < 16; ++it) {
            int idx = tid + it * 256;
            int cl = idx >> 7, pxl = idx & 127;
            int c = k0 + cl;
            float hv = g_h[((size_t)b * C1n + c) * PXn + pxb + pxl];
            float z = g_a1[c] * hv + g_b1[c];
            __half h = __float2half(z);
            As[0][cl][pxl] = h;
            As[1][cl][pxl] = __float2half(z - __half2float(h));
        }
#pragma unroll
        for (int p = 0; p < 2; ++p)
#pragma unroll
            for (int it = 0; it < 8; ++it) {
                int idx = tid + it * 256;
                int oc = idx >> 4, kk2 = idx & 15;
                *(u32*)&Bs[p][oc][kk2 * 2] =
                    *(const u32*)&g_w2h[p][(size_t)(ocb + oc) * C1n + k0 + kk2 * 2];
            }
        __syncthreads();
#pragma unroll
        for (int ks = 0; ks < 2; ++ks) {
            u32 ah[2][4], al[2][4];
#pragma unroll
            for (int mt = 0; mt < 2; ++mt) {
                u32 aa = smem_u32(&As[0][ks * 16 + arow][acol + mt * 16]);
                LDSM4T(ah[mt][0], ah[mt][1], ah[mt][2], ah[mt][3], aa);
                aa = smem_u32(&As[1][ks * 16 + arow][acol + mt * 16]);
                LDSM4T(al[mt][0], al[mt][1], al[mt][2], al[mt][3], aa);
            }
#pragma unroll
            for (int p = 0; p < 4; ++p) {
                u32 bh[4], bl[4];
                u32 ba = smem_u32(&Bs[0][wn * 64 + p * 16 + lrow][ks * 16 + lkof]);
                LDSM4(bh[0], bh[1], bh[2], bh[3], ba);
                ba = smem_u32(&Bs[1][wn * 64 + p * 16 + lrow][ks * 16 + lkof]);
                LDSM4(bl[0], bl[1], bl[2], bl[3], ba);
#pragma unroll
                for (int mt = 0; mt < 2; ++mt)
#pragma unroll
                    for (int o = 0; o < 2; ++o) {
                        int nt = p * 2 + o;
                        MMA16816(acc[mt][nt], ah[mt][0], ah[mt][1], ah[mt][2], ah[mt][3], bh[o], bh[o + 2]);
                        MMA16816(acc[mt][nt], ah[mt][0], ah[mt][1], ah[mt][2], ah[mt][3], bl[o], bl[o + 2]);
                        MMA16816(acc[mt][nt], al[mt][0], al[mt][1], al[mt][2], al[mt][3], bh[o], bh[o + 2]);
                    }
            }
        }
    }

    const int r0 = lane >> 2, c4 = lane & 3;
    float* kb = g_k + (size_t)b * PXn * OCn;
#pragma unroll
    for (int mt = 0; mt < 2; ++mt) {
        int px0 = pxb + wm * 32 + mt * 16 + r0;
#pragma unroll
        for (int nt = 0; nt < 8; ++nt) {
            int oc = ocb + wn * 64 + nt * 8 + c4 * 2;
            float b0v = cb2[oc], b1v = cb2[oc + 1];
            float2 v0; v0.x = acc[mt][nt][0] + b0v; v0.y = acc[mt][nt][1] + b1v;
            float2 v1; v1.x = acc[mt][nt][2] + b0v; v1.y = acc[mt][nt][3] + b1v;
            *(float2*)&kb[(size_t)px0 * OCn + oc] = v0;
            *(float2*)&kb[(size_t)(px0 + 8) * OCn + oc] = v1;
        }
    }
}

// ============================================================================
// K5/K6: BN2 stats + finalize
// ============================================================================
__global__ void __launch_bounds__(256) k_stats2() {
    const int lane = threadIdx.x & 31, row = threadIdx.x >> 5;
    const int oc = blockIdx.x * 32 + lane;
    const int r0 = blockIdx.y * 4096;
    float s = 0.f, q = 0.f;
    for (int r = r0 + row; r < r0 + 4096; r += 8) {
        float v = g_k[(size_t)r * OCn + oc];
        s += v; q += v * v;
    }
    __shared__ float ss[8][33], qs[8][33];
    ss[row][lane] = s; qs[row][lane] = q;
    __syncthreads();
    if (row == 0) {
#pragma unroll
        for (int i = 1; i < 8; i++) { s += ss[i][lane]; q += qs[i][lane]; }
        g_p2s[blockIdx.y * OCn + oc] = s;
        g_p2q[blockIdx.y * OCn + oc] = q;
    }
}

__global__ void k_fin2(const float* __restrict__ g, const float* __restrict__ bb) {
    const int oc = threadIdx.x;
    float s = 0.f, q = 0.f;
#pragma unroll
    for (int i = 0; i < 16; i++) { s += g_p2s[i * OCn + oc]; q += g_p2q[i * OCn + oc]; }
    const float inv = 1.0f / 65536.0f;
    float m = s * inv;
    float var = q * inv - m * m;
    float a = g[oc] * rsqrtf(var + 1e-5f);
    g_a2[oc] = a;
    g_b2[oc] = bb[oc] - m * a;
}

// ============================================================================
// K7: fused BN2-affine + softmax; emits fp16 hi/lo split directly (g_kh)
// ============================================================================
__global__ void __launch_bounds__(128) k_softmax() {
    __shared__ float red[8];
    const float* row = g_k + (size_t)blockIdx.x * OCn;
    const int t = threadIdx.x;
    const int lane = t & 31, wid = t >> 5;

    float4 v0 = *reinterpret_cast<const float4*>(row + t * 4);
    float4 v1 = *reinterpret_cast<const float4*>(row + 512 + t * 4);
    float4 a0 = *reinterpret_cast<const float4*>(g_a2 + t * 4);
    float4 a1 = *reinterpret_cast<const float4*>(g_a2 + 512 + t * 4);
    float4 b0 = *reinterpret_cast<const float4*>(g_b2 + t * 4);
    float4 b1 = *reinterpret_cast<const float4*>(g_b2 + 512 + t * 4);

    float z[8];
    z[0] = a0.x * v0.x + b0.x; z[1] = a0.y * v0.y + b0.y;
    z[2] = a0.z * v0.z + b0.z; z[3] = a0.w * v0.w + b0.w;
    z[4] = a1.x * v1.x + b1.x; z[5] = a1.y * v1.y + b1.y;
    z[6] = a1.z * v1.z + b1.z; z[7] = a1.w * v1.w + b1.w;

    float m = z[0];
#pragma unroll
    for (int i = 1; i < 8; i++) m = fmaxf(m, z[i]);
#pragma unroll
    for (int o = 16; o > 0; o >>= 1) m = fmaxf(m, __shfl_xor_sync(0xffffffffu, m, o));
    if (lane == 0) red[wid] = m;
    __syncthreads();
    m = fmaxf(fmaxf(red[0], red[1]), fmaxf(red[2], red[3]));

    float s = 0.f;
#pragma unroll
    for (int i = 0; i < 8; i++) { z[i] = __expf(z[i] - m); s += z[i]; }
#pragma unroll
    for (int o = 16; o > 0; o >>= 1) s += __shfl_xor_sync(0xffffffffu, s, o);
    if (lane == 0) red[4 + wid] = s;
    __syncthreads();
    s = (red[4] + red[5]) + (red[6] + red[7]);
    float inv = 1.0f / s;

    __half2* rh = (__half2*)(g_kh[0] + (size_t)blockIdx.x * OCn);
    __half2* rl = (__half2*)(g_kh[1] + (size_t)blockIdx.x * OCn);
#pragma unroll
    for (int hblk = 0; hblk < 2; ++hblk) {
#pragma unroll
        for (int pr = 0; pr < 2; ++pr) {
            float va = z[hblk * 4 + pr * 2] * inv;
            float vb = z[hblk * 4 + pr * 2 + 1] * inv;
            __half ha = __float2half(va), hb = __float2half(vb);
            int idx = hblk * 256 + t * 2 + pr;
            rh[idx] = __halves2half2(ha, hb);
            rl[idx] = __halves2half2(__float2half(va - __half2float(ha)),
                                     __float2half(vb - __half2float(hb)));
        }
    }
}

// ============================================================================
// K8: final einsum GEMM per batch, tensor cores (fp16 hi/lo split):
//   out[b][ij][c] = sum_uv kmap[ij][uv] * x[c][uv]
// A = g_kh rows [ij][uv], B = g_xn rows [c][uv]; both non-trans ldmatrix.
// Block: 128 ij x 128 c. 8 warps (4m x 2n), warp: 32 ij x 64 c. K=1024.
// ============================================================================
__global__ void __launch_bounds__(256, 2)
k_final(float* __restrict__ out) {
    __shared__ __align__(16) __half As[2][128][40];   // [prec][m=ij][k pad40]
    __shared__ __align__(16) __half Bs[2][128][40];   // [prec][n=c][k pad40]
    const int tid = threadIdx.x;
    const int lane = tid & 31, wid = tid >> 5;
    const int cb = blockIdx.x * 128, ijb = blockIdx.y * 128, b = blockIdx.z;
    const int wm = wid & 3, wn = wid >> 2;

    float acc[2][8][4];
#pragma unroll
    for (int m = 0; m < 2; m++)
#pragma unroll
        for (int n = 0; n < 8; n++)
#pragma unroll
            for (int q = 0; q < 4; q++) acc[m][n][q] = 0.f;

    const int lrow = lane & 15, lkof = (lane >> 4) * 8;

#pragma unroll 1
    for (int u0 = 0; u0 < OCn; u0 += 32) {
        __syncthreads();
#pragma unroll
        for (int p = 0; p < 2; ++p)
#pragma unroll
            for (int it = 0; it < 8; ++it) {
                int idx = tid + it * 256;
                int ij = idx >> 4, kk2 = idx & 15;
                *(u32*)&As[p][ij][kk2 * 2] =
                    *(const u32*)&g_kh[p][((size_t)(b * PXn) + ijb + ij) * OCn + u0 + kk2 * 2];
            }
#pragma unroll
        for (int p = 0; p < 2; ++p)
#pragma unroll
            for (int it = 0; it < 8; ++it) {
                int idx = tid + it * 256;
                int c = idx >> 4, kk2 = idx & 15;
                *(u32*)&Bs[p][c][kk2 * 2] =
                    *(const u32*)&g_xn[p][((size_t)(b * Cn) + cb + c) * PXn + u0 + kk2 * 2];
            }
        __syncthreads();
#pragma unroll
        for (int ks = 0; ks < 2; ++ks) {
            u32 ah[2][4], al[2][4];
#pragma unroll
            for (int mt = 0; mt < 2; ++mt) {
                u32 aa = smem_u32(&As[0][wm * 32 + mt * 16 + lrow][ks * 16 + lkof]);
                LDSM4(ah[mt][0], ah[mt][1], ah[mt][2], ah[mt][3], aa);
                aa = smem_u32(&As[1][wm * 32 + mt * 16 + lrow][ks * 16 + lkof]);
                LDSM4(al[mt][0], al[mt][1], al[mt][2], al[mt][3], aa);
            }
#pragma unroll
            for (int p = 0; p < 4; ++p) {
                u32 bh[4], bl[4];
                u32 ba = smem_u32(&Bs[0][wn * 64 + p * 16 + lrow][ks * 16 + lkof]);
                LDSM4(bh[0], bh[1], bh[2], bh[3], ba);
                ba = smem_u32(&Bs[1][wn * 64 + p * 16 + lrow][ks * 16 + lkof]);
                LDSM4(bl[0], bl[1], bl[2], bl[3], ba);
#pragma unroll
                for (int mt = 0; mt < 2; ++mt)
#pragma unroll
                    for (int o = 0; o < 2; ++o) {
                        int nt = p * 2 + o;
                        MMA16816(acc[mt][nt], ah[mt][0], ah[mt][1], ah[mt][2], ah[mt][3], bh[o], bh[o + 2]);
                        MMA16816(acc[mt][nt], ah[mt][0], ah[mt][1], ah[mt][2], ah[mt][3], bl[o], bl[o + 2]);
                        MMA16816(acc[mt][nt], al[mt][0], al[mt][1], al[mt][2], al[mt][3], bh[o], bh[o + 2]);
                    }
            }
        }
    }

    const int r0 = lane >> 2, c4 = lane & 3;
    float* ob = out + (size_t)b * PXn * Cn;
#pragma unroll
    for (int mt = 0; mt < 2; ++mt) {
        int ij = ijb + wm * 32 + mt * 16 + r0;
#pragma unroll
        for (int nt = 0; nt < 8; ++nt) {
            int cc = cb + wn * 64 + nt * 8 + c4 * 2;
            float2 v0; v0.x = acc[mt][nt][0]; v0.y = acc[mt][nt][1];
            float2 v1; v1.x = acc[mt][nt][2]; v1.y = acc[mt][nt][3];
            *(float2*)&ob[(size_t)ij * Cn + cc] = v0;
            *(float2*)&ob[(size_t)(ij + 8) * Cn + cc] = v1;
        }
    }
}

// ============================================================================
extern "C" void kernel_launch(void* const* d_in, const int* in_sizes, int n_in,
                              void* d_out, int out_size) {
    (void)in_sizes; (void)n_in; (void)out_size;
    const float* x   = (const float*)d_in[0];
    const float* w1  = (const float*)d_in[1];
    const float* cb1 = (const float*)d_in[2];
    const float* g1  = (const float*)d_in[3];
    const float* bb1 = (const float*)d_in[4];
    const float* w2  = (const float*)d_in[5];
    const float* cb2 = (const float*)d_in[6];
    const float* g2  = (const float*)d_in[7];
    const float* bb2 = (const float*)d_in[8];
    float* out = (float*)d_out;

    k_prep_w <<<49, 256>>>(w1);
    k_prep_w2<<<256, 256>>>(w2);
    k_prep_x <<<dim3(Cn, Bn), 256>>>(x);
    k_conv1  <<<dim3(4, 4, Bn), 256>>>(cb1);
    k_stats1 <<<dim3(C1n, 8), 256>>>();
    k_fin1   <<<1, C1n>>>(g1, bb1);
    k_conv2  <<<dim3(8, 8, Bn), 256>>>(cb2);
    k_stats2 <<<dim3(32, 16), 256>>>();
    k_fin2   <<<1, OCn>>>(g2, bb2);
    k_softmax<<<Bn * PXn, 128>>>();
    k_final  <<<dim3(2, 8, Bn), 256>>>(out);
}

// round 14
// speedup vs baseline: 2.3357x; 1.0409x over previous
#include <cuda_runtime.h>
#include <cuda_fp16.h>

typedef unsigned long long u64;
typedef unsigned int u32;

#define Bn   64
#define Cn   256
#define HWn  32
#define PXn  1024
#define C1n  256
#define OCn  1024

// ---------------- scratch (device globals; no allocation allowed) ----------
__device__ __align__(16) float g_h[Bn * C1n * PXn];          // 67 MB  [b][c1][px]
__device__ __align__(16) float g_k[(size_t)Bn * PXn * OCn];  // 268 MB [b][ij][uv] (pre-BN2 z)
__device__ float g_p1s[8 * C1n],  g_p1q[8 * C1n];
__device__ float g_a1[C1n], g_b1[C1n];
__device__ float g_p2s[OCn], g_p2q[OCn];                     // fused-atomic BN2 partials
__device__ __align__(16) float g_a2[OCn];
__device__ __align__(16) float g_b2[OCn];
// fp16 hi/lo split operands
__device__ __align__(16) __half g_wt[2][49 * 256 * 256];                 // conv1 W [prec][tap][oc][c]
__device__ __align__(16) __half g_xp[2][(size_t)Bn * 4 * 256 * 256];     // conv1 x [prec][b][par][c][px]
__device__ __align__(16) __half g_w2h[2][OCn * C1n];                     // conv2 W [prec][oc][c]
__device__ __align__(16) __half g_xn[2][(size_t)Bn * Cn * PXn];          // final x [prec][b][c][uv]
__device__ __align__(16) __half g_kh[2][(size_t)Bn * PXn * OCn];         // softmax out [prec][b][ij][uv]

__device__ __forceinline__ u32 smem_u32(const void* p) {
    return (u32)__cvta_generic_to_shared(p);
}

#define LDSM4(R0,R1,R2,R3,A) \
  asm volatile("ldmatrix.sync.aligned.m8n8.x4.shared.b16 {%0,%1,%2,%3}, [%4];" \
    : "=r"(R0),"=r"(R1),"=r"(R2),"=r"(R3) : "r"(A))

#define LDSM4T(R0,R1,R2,R3,A) \
  asm volatile("ldmatrix.sync.aligned.m8n8.x4.trans.shared.b16 {%0,%1,%2,%3}, [%4];" \
    : "=r"(R0),"=r"(R1),"=r"(R2),"=r"(R3) : "r"(A))

#define MMA16816(C,A0,A1,A2,A3,B0,B1) \
  asm volatile("mma.sync.aligned.m16n8k16.row.col.f32.f16.f16.f32 " \
    "{%0,%1,%2,%3},{%4,%5,%6,%7},{%8,%9},{%0,%1,%2,%3};" \
    : "+f"(C[0]),"+f"(C[1]),"+f"(C[2]),"+f"(C[3]) \
    : "r"(A0),"r"(A1),"r"(A2),"r"(A3),"r"(B0),"r"(B1))

#define CP16(DST,SRC) \
  asm volatile("cp.async.cg.shared.global [%0], [%1], 16;" :: "r"(DST), "l"(SRC))
#define CPCOMMIT() asm volatile("cp.async.commit_group;")
#define CPWAIT0()  asm volatile("cp.async.wait_group 0;" ::: "memory")

// conv1 dynamic smem layout:
//   xs: [2 prec][484*16]        = 30976 B
//   ws: [2 buf][7 tap][2 prec][64 oc][24 halves] = 86016 B
#define C1_XS_BYTES 30976
#define C1_SMEM     (30976 + 86016)

// ============================================================================
// P1: split conv1 weights into fp16 hi/lo, layout [prec][tap][oc][c]
// ============================================================================
__global__ void k_prep_w(const float* __restrict__ w1) {
    const int tap = blockIdx.x;
    for (int i = threadIdx.x; i < 65536; i += 256) {      // i = oc*256 + c
        float v = w1[(size_t)i * 49 + tap];
        __half h = __float2half(v);
        __half l = __float2half(v - __half2float(h));
        g_wt[0][(size_t)tap * 65536 + i] = h;
        g_wt[1][(size_t)tap * 65536 + i] = l;
    }
}

// ============================================================================
// P1b: split conv2 weights into fp16 hi/lo, layout [prec][oc][c].
// Block 0 also zeroes the fused BN2-stat accumulators (runs before k_conv2).
// ============================================================================
__global__ void k_prep_w2(const float* __restrict__ w2) {
    if (blockIdx.x == 0) {
#pragma unroll
        for (int r = 0; r < 4; ++r) {
            g_p2s[threadIdx.x * 4 + r] = 0.f;
            g_p2q[threadIdx.x * 4 + r] = 0.f;
        }
    }
    int i = blockIdx.x * 1024 + threadIdx.x;
#pragma unroll
    for (int r = 0; r < 4; ++r, i += 256) {
        float v = w2[i];
        __half h = __float2half(v);
        g_w2h[0][i] = h;
        g_w2h[1][i] = __float2half(v - __half2float(h));
    }
}

// ============================================================================
// P2: split x into fp16 hi/lo: parity subgrids (conv1) + native [c][uv] (final)
// ============================================================================
__global__ void k_prep_x(const float* __restrict__ x) {
    const int c = blockIdx.x, b = blockIdx.y;
    const int px = threadIdx.x;                     // 0..255
    const int si = px >> 4, sj = px & 15;
    const float* xc = x + ((size_t)b * Cn + c) * PXn;
#pragma unroll
    for (int par = 0; par < 4; ++par) {
        int fi = 2 * si + (par >> 1), fj = 2 * sj + (par & 1);
        float v = xc[fi * HWn + fj];
        __half h = __float2half(v);
        __half l = __float2half(v - __half2float(h));
        size_t o = (((size_t)b * 4 + par) * 256 + c) * 256 + px;
        g_xp[0][o] = h;
        g_xp[1][o] = l;
        size_t on = ((size_t)b * Cn + c) * PXn + fi * HWn + fj;
        g_xn[0][on] = h;
        g_xn[1][on] = l;
    }
}

// ============================================================================
// K1: conv1 7x7 dilation-2 pad-6 via 4 parity subgrids, tensor cores.
// Weight staging: one cp.async group per kh-ROW (7 taps, 28KB), double
// buffered -> 8 syncs per c-chunk instead of 50, prefetch a full row ahead.
// ============================================================================
__global__ void __launch_bounds__(256, 1)
k_conv1(const float* __restrict__ cb1) {
    extern __shared__ __align__(16) char dynsm[];
    __half* xs = (__half*)dynsm;                       // [2][7744]
    __half* ws = (__half*)(dynsm + C1_XS_BYTES);       // [2][7][2][64][24]

    const int tid = threadIdx.x;
    const int lane = tid & 31, wid = tid >> 5;
    const int ocb = blockIdx.x * 64;
    const int par = blockIdx.y;
    const int pi = par >> 1, pj = par & 1;
    const int b = blockIdx.z;

    for (int i = tid; i < 7744; i += 256) {
        xs[i] = __float2half(0.f);
        xs[7744 + i] = __float2half(0.f);
    }

    float acc[2][8][4];
#pragma unroll
    for (int m = 0; m < 2; m++)
#pragma unroll
        for (int n = 0; n < 8; n++)
#pragma unroll
            for (int q = 0; q < 4; q++) acc[m][n][q] = 0.f;

    // per-thread weight staging slice: (prec, oc, 8-half half-row)
    const int sprec = tid >> 7;
    const int soc   = (tid & 127) >> 1;
    const int shalf = tid & 1;
    const __half* wsrc0 = g_wt[sprec] + (size_t)(ocb + soc) * 256 + shalf * 8;
    const u32 wsa = smem_u32(ws);
    const u32 mydst = wsa + (u32)(sprec * 3072 + soc * 48 + shalf * 16);

    const __half* xp0 = g_xp[0] + (((size_t)b * 4 + par) * 256) * 256;
    const __half* xp1 = g_xp[1] + (((size_t)b * 4 + par) * 256) * 256;

    const int lrow = lane & 15;
    const int lkof = (lane >> 4) * 8;
    const u32 xsa = smem_u32(xs);

    for (int cc = 0; cc < 16; ++cc) {
        const int c0 = cc * 16;
        __syncthreads();   // all reads of xs and ws buf0 (kh=6) complete
        const __half* wsrc_c = wsrc0 + c0;
        // stage kh=0 row into buf 0
#pragma unroll
        for (int t = 0; t < 7; ++t)
            CP16(mydst + (u32)(t * 6144), wsrc_c + (size_t)t * 65536);
        CPCOMMIT();
        // load input subgrid chunk (overlaps with staging latency)
        for (int i = tid; i < 4096; i += 256) {
            int c = i >> 8, px = i & 255;
            int si = px >> 4, sj = px & 15;
            int d = ((si + 3) * 22 + (sj + 3)) * 16 + c;
            xs[d] = xp0[(size_t)(c0 + c) * 256 + px];
            xs[7744 + d] = xp1[(size_t)(c0 + c) * 256 + px];
        }

#pragma unroll 1
        for (int kh = 0; kh < 7; ++kh) {
            const int buf = kh & 1;
            CPWAIT0();
            __syncthreads();
            if (kh < 6) {
                const __half* s2 = wsrc_c + (size_t)((kh + 1) * 7) * 65536;
                const u32 d2 = mydst + (u32)((buf ^ 1) * 43008);
#pragma unroll
                for (int t = 0; t < 7; ++t)
                    CP16(d2 + (u32)(t * 6144), s2 + (size_t)t * 65536);
                CPCOMMIT();
            }
#pragma unroll 1
            for (int kw = 0; kw < 7; ++kw) {
                const u32 bbase = wsa + (u32)((buf * 7 + kw) * 6144);
                u32 bh[4][4], bl[4][4];
#pragma unroll
                for (int p = 0; p < 4; ++p) {
                    u32 a0 = bbase + (u32)((p * 16 + lrow) * 48 + lkof * 2);
                    LDSM4(bh[p][0], bh[p][1], bh[p][2], bh[p][3], a0);
                    LDSM4(bl[p][0], bl[p][1], bl[p][2], bl[p][3], a0 + 3072u);
                }
#pragma unroll
                for (int mt = 0; mt < 2; ++mt) {
                    int pixr = (2 * wid + mt + kh) * 22 + lrow + kw;
                    u32 aadr = xsa + (u32)((pixr * 16 + lkof) * 2);
                    u32 ah[4], al[4];
                    LDSM4(ah[0], ah[1], ah[2], ah[3], aadr);
                    LDSM4(al[0], al[1], al[2], al[3], aadr + (u32)(7744 * 2));
#pragma unroll
                    for (int nt = 0; nt < 8; ++nt) {
                        int p = nt >> 1, o = nt & 1;
                        MMA16816(acc[mt][nt], ah[0], ah[1], ah[2], ah[3], bh[p][o], bh[p][o + 2]);
                    }
#pragma unroll
                    for (int nt = 0; nt < 8; ++nt) {
                        int p = nt >> 1, o = nt & 1;
                        MMA16816(acc[mt][nt], ah[0], ah[1], ah[2], ah[3], bl[p][o], bl[p][o + 2]);
                    }
#pragma unroll
                    for (int nt = 0; nt < 8; ++nt) {
                        int p = nt >> 1, o = nt & 1;
                        MMA16816(acc[mt][nt], al[0], al[1], al[2], al[3], bh[p][o], bh[p][o + 2]);
                    }
                }
            }
        }
    }

    const int sj0 = lane >> 2;
    const int ocl = 2 * (lane & 3);
    float* hb = g_h + (size_t)b * C1n * PXn;
#pragma unroll
    for (int mt = 0; mt < 2; ++mt) {
        int si = 2 * wid + mt;
        int fi = 2 * si + pi;
#pragma unroll
        for (int nt = 0; nt < 8; ++nt) {
            int oc = ocb + nt * 8 + ocl;
            float bz0 = cb1[oc], bz1 = cb1[oc + 1];
            int fja = 2 * sj0 + pj, fjb = 2 * (sj0 + 8) + pj;
            hb[(size_t)oc * PXn + fi * HWn + fja]       = acc[mt][nt][0] + bz0;
            hb[(size_t)(oc + 1) * PXn + fi * HWn + fja] = acc[mt][nt][1] + bz1;
            hb[(size_t)oc * PXn + fi * HWn + fjb]       = acc[mt][nt][2] + bz0;
            hb[(size_t)(oc + 1) * PXn + fi * HWn + fjb] = acc[mt][nt][3] + bz1;
        }
    }
}

// ============================================================================
// K2/K3: BN1 batch stats + finalize
// ============================================================================
__global__ void __launch_bounds__(256) k_stats1() {
    const int c = blockIdx.x;
    const int b0 = blockIdx.y * 8;
    float s = 0.f, q = 0.f;
    for (int b = b0; b < b0 + 8; ++b) {
        const float* hp = g_h + ((size_t)b * C1n + c) * PXn;
        for (int px = threadIdx.x; px < PXn; px += 256) {
            float v = hp[px]; s += v; q += v * v;
        }
    }
    __shared__ float ss[256], qs[256];
    ss[threadIdx.x] = s; qs[threadIdx.x] = q;
    __syncthreads();
    for (int o = 128; o > 0; o >>= 1) {
        if (threadIdx.x < o) {
            ss[threadIdx.x] += ss[threadIdx.x + o];
            qs[threadIdx.x] += qs[threadIdx.x + o];
        }
        __syncthreads();
    }
    if (threadIdx.x == 0) {
        g_p1s[blockIdx.y * C1n + c] = ss[0];
        g_p1q[blockIdx.y * C1n + c] = qs[0];
    }
}

__global__ void k_fin1(const float* __restrict__ g, const float* __restrict__ bb) {
    const int c = threadIdx.x;
    float s = 0.f, q = 0.f;
#pragma unroll
    for (int i = 0; i < 8; i++) { s += g_p1s[i * C1n + c]; q += g_p1q[i * C1n + c]; }
    const float inv = 1.0f / 65536.0f;
    float m = s * inv;
    float var = q * inv - m * m;
    float a = g[c] * rsqrtf(var + 1e-5f);
    g_a1[c] = a;
    g_b1[c] = bb[c] - m * a;
}

// ============================================================================
// K4: conv2 1x1 GEMM per batch, tensor cores (fp16 hi/lo split).
// Epilogue also accumulates BN2 batch stats (warp reduce + global atomics),
// replacing the separate k_stats2 pass over 268MB.
// ============================================================================
__global__ void __launch_bounds__(256, 2)
k_conv2(const float* __restrict__ cb2) {
    __shared__ __align__(16) __half As[2][32][136];   // [prec][k=c][m=px pad136]
    __shared__ __align__(16) __half Bs[2][128][40];   // [prec][n=oc][k=c pad40]
    const int tid = threadIdx.x;
    const int lane = tid & 31, wid = tid >> 5;
    const int pxb = blockIdx.x * 128, ocb = blockIdx.y * 128, b = blockIdx.z;
    const int wm = wid & 3, wn = wid >> 2;

    float acc[2][8][4];
#pragma unroll
    for (int m = 0; m < 2; m++)
#pragma unroll
        for (int n = 0; n < 8; n++)
#pragma unroll
            for (int q = 0; q < 4; q++) acc[m][n][q] = 0.f;

    const int arow = (lane & 7) + ((lane >> 4) & 1) * 8;
    const int acol = ((lane >> 3) & 1) * 8 + wm * 32;
    const int lrow = lane & 15, lkof = (lane >> 4) * 8;

#pragma unroll 1
    for (int k0 = 0; k0 < C1n; k0 += 32) {
        __syncthreads();
#pragma unroll
        for (int it = 0; it < 16; ++it) {
            int idx = tid + it * 256;
            int cl = idx >> 7, pxl = idx & 127;
            int c = k0 + cl;
            float hv = g_h[((size_t)b * C1n + c) * PXn + pxb + pxl];
            float z = g_a1[c] * hv + g_b1[c];
            __half h = __float2half(z);
            As[0][cl][pxl] = h;
            As[1][cl][pxl] = __float2half(z - __half2float(h));
        }
#pragma unroll
        for (int p = 0; p < 2; ++p)
#pragma unroll
            for (int it = 0; it < 8; ++it) {
                int idx = tid + it * 256;
                int oc = idx >> 4, kk2 = idx & 15;
                *(u32*)&Bs[p][oc][kk2 * 2] =
                    *(const u32*)&g_w2h[p][(size_t)(ocb + oc) * C1n + k0 + kk2 * 2];
            }
        __syncthreads();
#pragma unroll
        for (int ks = 0; ks < 2; ++ks) {
            u32 ah[2][4], al[2][4];
#pragma unroll
            for (int mt = 0; mt < 2; ++mt) {
                u32 aa = smem_u32(&As[0][ks * 16 + arow][acol + mt * 16]);
                LDSM4T(ah[mt][0], ah[mt][1], ah[mt][2], ah[mt][3], aa);
                aa = smem_u32(&As[1][ks * 16 + arow][acol + mt * 16]);
                LDSM4T(al[mt][0], al[mt][1], al[mt][2], al[mt][3], aa);
            }
#pragma unroll
            for (int p = 0; p < 4; ++p) {
                u32 bh[4], bl[4];
                u32 ba = smem_u32(&Bs[0][wn * 64 + p * 16 + lrow][ks * 16 + lkof]);
                LDSM4(bh[0], bh[1], bh[2], bh[3], ba);
                ba = smem_u32(&Bs[1][wn * 64 + p * 16 + lrow][ks * 16 + lkof]);
                LDSM4(bl[0], bl[1], bl[2], bl[3], ba);
#pragma unroll
                for (int mt = 0; mt < 2; ++mt)
#pragma unroll
                    for (int o = 0; o < 2; ++o) {
                        int nt = p * 2 + o;
                        MMA16816(acc[mt][nt], ah[mt][0], ah[mt][1], ah[mt][2], ah[mt][3], bh[o], bh[o + 2]);
                        MMA16816(acc[mt][nt], ah[mt][0], ah[mt][1], ah[mt][2], ah[mt][3], bl[o], bl[o + 2]);
                        MMA16816(acc[mt][nt], al[mt][0], al[mt][1], al[mt][2], al[mt][3], bh[o], bh[o + 2]);
                    }
            }
        }
    }

    const int r0 = lane >> 2, c4 = lane & 3;
    float* kb = g_k + (size_t)b * PXn * OCn;
#pragma unroll
    for (int nt = 0; nt < 8; ++nt) {
        int oc = ocb + wn * 64 + nt * 8 + c4 * 2;
        float b0v = cb2[oc], b1v = cb2[oc + 1];
        float z[2][4];
#pragma unroll
        for (int mt = 0; mt < 2; ++mt) {
            z[mt][0] = acc[mt][nt][0] + b0v; z[mt][1] = acc[mt][nt][1] + b1v;
            z[mt][2] = acc[mt][nt][2] + b0v; z[mt][3] = acc[mt][nt][3] + b1v;
            int px0 = pxb + wm * 32 + mt * 16 + r0;
            *(float2*)&kb[(size_t)px0 * OCn + oc] = make_float2(z[mt][0], z[mt][1]);
            *(float2*)&kb[(size_t)(px0 + 8) * OCn + oc] = make_float2(z[mt][2], z[mt][3]);
        }
        // BN2 partial sums over the 32 px this warp owns for this oc pair
        float s0 = z[0][0] + z[0][2] + z[1][0] + z[1][2];
        float s1 = z[0][1] + z[0][3] + z[1][1] + z[1][3];
        float q0 = z[0][0] * z[0][0] + z[0][2] * z[0][2] + z[1][0] * z[1][0] + z[1][2] * z[1][2];
        float q1 = z[0][1] * z[0][1] + z[0][3] * z[0][3] + z[1][1] * z[1][1] + z[1][3] * z[1][3];
#pragma unroll
        for (int o = 4; o <= 16; o <<= 1) {
            s0 += __shfl_xor_sync(0xffffffffu, s0, o);
            s1 += __shfl_xor_sync(0xffffffffu, s1, o);
            q0 += __shfl_xor_sync(0xffffffffu, q0, o);
            q1 += __shfl_xor_sync(0xffffffffu, q1, o);
        }
        if (r0 == 0) {
            atomicAdd(&g_p2s[oc], s0);     atomicAdd(&g_p2q[oc], q0);
            atomicAdd(&g_p2s[oc + 1], s1); atomicAdd(&g_p2q[oc + 1], q1);
        }
    }
}

// ============================================================================
// K6: BN2 finalize (partials already accumulated by k_conv2)
// ============================================================================
__global__ void k_fin2(const float* __restrict__ g, const float* __restrict__ bb) {
    const int oc = threadIdx.x;
    float s = g_p2s[oc], q = g_p2q[oc];
    const float inv = 1.0f / 65536.0f;
    float m = s * inv;
    float var = q * inv - m * m;
    float a = g[oc] * rsqrtf(var + 1e-5f);
    g_a2[oc] = a;
    g_b2[oc] = bb[oc] - m * a;
}

// ============================================================================
// K7: fused BN2-affine + softmax; emits fp16 hi/lo split directly (g_kh)
// ============================================================================
__global__ void __launch_bounds__(128) k_softmax() {
    __shared__ float red[8];
    const float* row = g_k + (size_t)blockIdx.x * OCn;
    const int t = threadIdx.x;
    const int lane = t & 31, wid = t >> 5;

    float4 v0 = *reinterpret_cast<const float4*>(row + t * 4);
    float4 v1 = *reinterpret_cast<const float4*>(row + 512 + t * 4);
    float4 a0 = *reinterpret_cast<const float4*>(g_a2 + t * 4);
    float4 a1 = *reinterpret_cast<const float4*>(g_a2 + 512 + t * 4);
    float4 b0 = *reinterpret_cast<const float4*>(g_b2 + t * 4);
    float4 b1 = *reinterpret_cast<const float4*>(g_b2 + 512 + t * 4);

    float z[8];
    z[0] = a0.x * v0.x + b0.x; z[1] = a0.y * v0.y + b0.y;
    z[2] = a0.z * v0.z + b0.z; z[3] = a0.w * v0.w + b0.w;
    z[4] = a1.x * v1.x + b1.x; z[5] = a1.y * v1.y + b1.y;
    z[6] = a1.z * v1.z + b1.z; z[7] = a1.w * v1.w + b1.w;

    float m = z[0];
#pragma unroll
    for (int i = 1; i < 8; i++) m = fmaxf(m, z[i]);
#pragma unroll
    for (int o = 16; o > 0; o >>= 1) m = fmaxf(m, __shfl_xor_sync(0xffffffffu, m, o));
    if (lane == 0) red[wid] = m;
    __syncthreads();
    m = fmaxf(fmaxf(red[0], red[1]), fmaxf(red[2], red[3]));

    float s = 0.f;
#pragma unroll
    for (int i = 0; i < 8; i++) { z[i] = __expf(z[i] - m); s += z[i]; }
#pragma unroll
    for (int o = 16; o > 0; o >>= 1) s += __shfl_xor_sync(0xffffffffu, s, o);
    if (lane == 0) red[4 + wid] = s;
    __syncthreads();
    s = (red[4] + red[5]) + (red[6] + red[7]);
    float inv = 1.0f / s;

    __half2* rh = (__half2*)(g_kh[0] + (size_t)blockIdx.x * OCn);
    __half2* rl = (__half2*)(g_kh[1] + (size_t)blockIdx.x * OCn);
#pragma unroll
    for (int hblk = 0; hblk < 2; ++hblk) {
#pragma unroll
        for (int pr = 0; pr < 2; ++pr) {
            float va = z[hblk * 4 + pr * 2] * inv;
            float vb = z[hblk * 4 + pr * 2 + 1] * inv;
            __half ha = __float2half(va), hb = __float2half(vb);
            int idx = hblk * 256 + t * 2 + pr;
            rh[idx] = __halves2half2(ha, hb);
            rl[idx] = __halves2half2(__float2half(va - __half2float(ha)),
                                     __float2half(vb - __half2float(hb)));
        }
    }
}

// ============================================================================
// K8: final einsum GEMM per batch, tensor cores (fp16 hi/lo split)
// ============================================================================
__global__ void __launch_bounds__(256, 2)
k_final(float* __restrict__ out) {
    __shared__ __align__(16) __half As[2][128][40];   // [prec][m=ij][k pad40]
    __shared__ __align__(16) __half Bs[2][128][40];   // [prec][n=c][k pad40]
    const int tid = threadIdx.x;
    const int lane = tid & 31, wid = tid >> 5;
    const int cb = blockIdx.x * 128, ijb = blockIdx.y * 128, b = blockIdx.z;
    const int wm = wid & 3, wn = wid >> 2;

    float acc[2][8][4];
#pragma unroll
    for (int m = 0; m < 2; m++)
#pragma unroll
        for (int n = 0; n < 8; n++)
#pragma unroll
            for (int q = 0; q < 4; q++) acc[m][n][q] = 0.f;

    const int lrow = lane & 15, lkof = (lane >> 4) * 8;

#pragma unroll 1
    for (int u0 = 0; u0 < OCn; u0 += 32) {
        __syncthreads();
#pragma unroll
        for (int p = 0; p < 2; ++p)
#pragma unroll
            for (int it = 0; it < 8; ++it) {
                int idx = tid + it * 256;
                int ij = idx >> 4, kk2 = idx & 15;
                *(u32*)&As[p][ij][kk2 * 2] =
                    *(const u32*)&g_kh[p][((size_t)(b * PXn) + ijb + ij) * OCn + u0 + kk2 * 2];
            }
#pragma unroll
        for (int p = 0; p < 2; ++p)
#pragma unroll
            for (int it = 0; it < 8; ++it) {
                int idx = tid + it * 256;
                int c = idx >> 4, kk2 = idx & 15;
                *(u32*)&Bs[p][c][kk2 * 2] =
                    *(const u32*)&g_xn[p][((size_t)(b * Cn) + cb + c) * PXn + u0 + kk2 * 2];
            }
        __syncthreads();
#pragma unroll
        for (int ks = 0; ks < 2; ++ks) {
            u32 ah[2][4], al[2][4];
#pragma unroll
            for (int mt = 0; mt < 2; ++mt) {
                u32 aa = smem_u32(&As[0][wm * 32 + mt * 16 + lrow][ks * 16 + lkof]);
                LDSM4(ah[mt][0], ah[mt][1], ah[mt][2], ah[mt][3], aa);
                aa = smem_u32(&As[1][wm * 32 + mt * 16 + lrow][ks * 16 + lkof]);
                LDSM4(al[mt][0], al[mt][1], al[mt][2], al[mt][3], aa);
            }
#pragma unroll
            for (int p = 0; p < 4; ++p) {
                u32 bh[4], bl[4];
                u32 ba = smem_u32(&Bs[0][wn * 64 + p * 16 + lrow][ks * 16 + lkof]);
                LDSM4(bh[0], bh[1], bh[2], bh[3], ba);
                ba = smem_u32(&Bs[1][wn * 64 + p * 16 + lrow][ks * 16 + lkof]);
                LDSM4(bl[0], bl[1], bl[2], bl[3], ba);
#pragma unroll
                for (int mt = 0; mt < 2; ++mt)
#pragma unroll
                    for (int o = 0; o < 2; ++o) {
                        int nt = p * 2 + o;
                        MMA16816(acc[mt][nt], ah[mt][0], ah[mt][1], ah[mt][2], ah[mt][3], bh[o], bh[o + 2]);
                        MMA16816(acc[mt][nt], ah[mt][0], ah[mt][1], ah[mt][2], ah[mt][3], bl[o], bl[o + 2]);
                        MMA16816(acc[mt][nt], al[mt][0], al[mt][1], al[mt][2], al[mt][3], bh[o], bh[o + 2]);
                    }
            }
        }
    }

    const int r0 = lane >> 2, c4 = lane & 3;
    float* ob = out + (size_t)b * PXn * Cn;
#pragma unroll
    for (int mt = 0; mt < 2; ++mt) {
        int ij = ijb + wm * 32 + mt * 16 + r0;
#pragma unroll
        for (int nt = 0; nt < 8; ++nt) {
            int cc = cb + wn * 64 + nt * 8 + c4 * 2;
            float2 v0; v0.x = acc[mt][nt][0]; v0.y = acc[mt][nt][1];
            float2 v1; v1.x = acc[mt][nt][2]; v1.y = acc[mt][nt][3];
            *(float2*)&ob[(size_t)ij * Cn + cc] = v0;
            *(float2*)&ob[(size_t)(ij + 8) * Cn + cc] = v1;
        }
    }
}

// ============================================================================
extern "C" void kernel_launch(void* const* d_in, const int* in_sizes, int n_in,
                              void* d_out, int out_size) {
    (void)in_sizes; (void)n_in; (void)out_size;
    const float* x   = (const float*)d_in[0];
    const float* w1  = (const float*)d_in[1];
    const float* cb1 = (const float*)d_in[2];
    const float* g1  = (const float*)d_in[3];
    const float* bb1 = (const float*)d_in[4];
    const float* w2  = (const float*)d_in[5];
    const float* cb2 = (const float*)d_in[6];
    const float* g2  = (const float*)d_in[7];
    const float* bb2 = (const float*)d_in[8];
    float* out = (float*)d_out;

    cudaFuncSetAttribute(k_conv1, cudaFuncAttributeMaxDynamicSharedMemorySize, C1_SMEM);

    k_prep_w <<<49, 256>>>(w1);
    k_prep_w2<<<256, 256>>>(w2);
    k_prep_x <<<dim3(Cn, Bn), 256>>>(x);
    k_conv1  <<<dim3(4, 4, Bn), 256, C1_SMEM>>>(cb1);
    k_stats1 <<<dim3(C1n, 8), 256>>>();
    k_fin1   <<<1, C1n>>>(g1, bb1);
    k_conv2  <<<dim3(8, 8, Bn), 256>>>(cb2);
    k_fin2   <<<1, OCn>>>(g2, bb2);
    k_softmax<<<Bn * PXn, 128>>>();
    k_final  <<<dim3(2, 8, Bn), 256>>>(out);
}